// round 3
// baseline (speedup 1.0000x reference)
#include <cuda_runtime.h>
#include <math.h>

// Problem shapes (fixed by setup_inputs)
#define BB 2
#define TT 512
#define MMs 512
#define DDim 512
#define HH 8
#define UU 64
#define OO 512
#define KVL 1024          // MMs + TT
#define NREL 1535         // KVL + TT - 1
#define LARGE_BIAS 10000.0f

// ---------------- scratch (static device globals; no allocation) ----------------
__device__ float g_S[NREL * DDim];                 // sinusoid table S[rel+511][d]   (3.1 MB)
__device__ float g_concat[BB * KVL * DDim];        // [state; inputs]                (4 MB)
__device__ float g_query[BB * TT * HH * UU];       // masked query (B,T,H,U)         (2 MB)
__device__ float g_key[BB * KVL * HH * UU];        // (B,KV,H,U)                     (4 MB)
__device__ float g_value[BB * KVL * HH * UU];      // (B,KV,H,U)                     (4 MB)
__device__ float g_relT[HH * UU * DDim];           // rel_W transposed to (h,u,d)    (1 MB)
__device__ float g_vrel[HH * DDim];                // v @ rel_W^T per head
__device__ float g_qv[BB * TT * HH * DDim];        // (B,T,H,D)                      (16 MB)
__device__ float g_ubias[BB * HH * KVL];           // key . u
__device__ float g_logits[BB * HH * TT * KVL];     // (B,H,T,KV) logits -> weights   (32 MB)
__device__ float g_att[BB * TT * HH * UU];         // attended (B,T,(H,U))           (2 MB)

// ---------------- table / prep kernels ----------------

// S[r][d] = sin((r-511)/wave_d + (pi/2)*(d&1)),  wave_d = 10000^(2d/512)
__global__ void k_tables() {
    int idx = blockIdx.x * blockDim.x + threadIdx.x;
    if (idx >= NREL * DDim) return;
    int r = idx / DDim;
    int d = idx - r * DDim;
    float rel = (float)(r - 511);
    float wave = powf(10000.0f, (2.0f * (float)d) / (float)DDim);
    float off  = (d & 1) ? 1.57079632679489662f : 0.0f;
    g_S[idx] = sinf(rel / wave + off);
}

__global__ void k_concat(const float* __restrict__ inputs, const float* __restrict__ state) {
    int idx = blockIdx.x * blockDim.x + threadIdx.x;
    if (idx >= BB * KVL * DDim) return;
    int d = idx & (DDim - 1);
    int j = (idx >> 9) & (KVL - 1);
    int b = idx >> 19;
    float v;
    if (j < MMs) v = state[((size_t)(b * MMs + j)) * DDim + d];
    else         v = inputs[((size_t)(b * TT + (j - MMs))) * DDim + d];
    g_concat[idx] = v;
}

// rel_W (d, h, u) -> g_relT (h, u, d)
__global__ void k_relT(const float* __restrict__ rW) {
    int idx = blockIdx.x * blockDim.x + threadIdx.x;
    if (idx >= DDim * HH * UU) return;
    int hu = idx & 511;
    int d  = idx >> 9;
    g_relT[(size_t)hu * DDim + d] = rW[idx];
}

// vrel[h][d] = sum_u v[h,u] * rel_W[d,h,u]
__global__ void k_vrel(const float* __restrict__ vv, const float* __restrict__ rW) {
    int idx = blockIdx.x * blockDim.x + threadIdx.x;
    if (idx >= HH * DDim) return;
    int h = idx >> 9;
    int d = idx & 511;
    const float* rp = rW + (size_t)d * (HH * UU) + h * UU;
    const float* vp = vv + h * UU;
    float s = 0.f;
#pragma unroll
    for (int u = 0; u < UU; u++) s = fmaf(rp[u], vp[u], s);
    g_vrel[idx] = s;
}

// ubias[(b,h,kv)] = sum_u key[b,kv,h,u] * u[h,u]
__global__ void k_ubias(const float* __restrict__ uW) {
    int idx = blockIdx.x * blockDim.x + threadIdx.x;
    if (idx >= BB * HH * KVL) return;
    int kv = idx & (KVL - 1);
    int h  = (idx >> 10) & (HH - 1);
    int b  = idx >> 13;
    const float* kp = g_key + ((size_t)(b * KVL + kv)) * (HH * UU) + h * UU;
    const float* up = uW + h * UU;
    float s = 0.f;
#pragma unroll
    for (int u = 0; u < UU; u++) s = fmaf(kp[u], up[u], s);
    g_ubias[idx] = s;
}

// ---------------- generic fp32 tiled GEMM: C = A @ B (+bias) (*rowmask) ----------------
// rowmask is int32 (bool inputs are materialized as int32 by the harness).
__global__ void __launch_bounds__(256) gemm64(
    const float* __restrict__ A, const float* __restrict__ Bm, float* __restrict__ C,
    int lda, int ldbk, int ldc, int Kdim,
    long a0, long b0, long c0,
    long az1, long az2, long bz1, long bz2, long cz1, long cz2,
    int Z2,
    const int* __restrict__ rowmask,
    const float* __restrict__ bias, long bias0, long biasz2)
{
    __shared__ float sA[16 * 64];
    __shared__ float sB[16 * 64];

    int z  = blockIdx.z;
    int z1 = z / Z2;
    int z2 = z - z1 * Z2;
    const float* Ap = A + a0 + (size_t)z1 * az1 + (size_t)z2 * az2;
    const float* Bp = Bm + b0 + (size_t)z1 * bz1 + (size_t)z2 * bz2;
    float*       Cp = C + c0 + (size_t)z1 * cz1 + (size_t)z2 * cz2;
    const float* biasp = bias ? (bias + bias0 + (size_t)z2 * biasz2) : (const float*)0;

    int m0 = blockIdx.y * 64;
    int n0 = blockIdx.x * 64;
    int tid = threadIdx.x;
    int tx = tid & 15, ty = tid >> 4;
    int am = tid >> 2, ak = (tid & 3) * 4;      // A loader: row am, k-group ak
    int bk = tid >> 4, bn = (tid & 15) * 4;     // B loader: k-row bk, n-group bn

    float acc[4][4];
#pragma unroll
    for (int i = 0; i < 4; i++)
#pragma unroll
        for (int j = 0; j < 4; j++) acc[i][j] = 0.f;

    for (int k0 = 0; k0 < Kdim; k0 += 16) {
        float4 av = *(const float4*)(Ap + (size_t)(m0 + am) * lda + (k0 + ak));
        float4 bv = *(const float4*)(Bp + (size_t)(k0 + bk) * ldbk + (n0 + bn));
        __syncthreads();
        sA[(ak + 0) * 64 + am] = av.x;
        sA[(ak + 1) * 64 + am] = av.y;
        sA[(ak + 2) * 64 + am] = av.z;
        sA[(ak + 3) * 64 + am] = av.w;
        *(float4*)&sB[bk * 64 + bn] = bv;
        __syncthreads();
#pragma unroll
        for (int kk = 0; kk < 16; kk++) {
            float4 a4 = *(const float4*)&sA[kk * 64 + ty * 4];
            float4 b4 = *(const float4*)&sB[kk * 64 + tx * 4];
            float a[4] = {a4.x, a4.y, a4.z, a4.w};
            float bb[4] = {b4.x, b4.y, b4.z, b4.w};
#pragma unroll
            for (int i = 0; i < 4; i++)
#pragma unroll
                for (int j = 0; j < 4; j++) acc[i][j] = fmaf(a[i], bb[j], acc[i][j]);
        }
    }

#pragma unroll
    for (int i = 0; i < 4; i++) {
        int mg = m0 + ty * 4 + i;
        float scale = 1.f;
        if (rowmask) scale = rowmask[mg] ? 1.f : 0.f;
        float4 o;
        float vals[4];
#pragma unroll
        for (int j = 0; j < 4; j++) {
            float v = acc[i][j];
            if (biasp) v += biasp[n0 + tx * 4 + j];
            vals[j] = v * scale;
        }
        o.x = vals[0]; o.y = vals[1]; o.z = vals[2]; o.w = vals[3];
        *(float4*)&Cp[(size_t)mg * ldc + n0 + tx * 4] = o;
    }
}

// ---------------- fused logits kernel ----------------
// logits[b,h,qt,kv] = ( Q.K^T + qv . S[qt-kv+512] + ubias[b,h,kv] ) / 8
//                     - causal LARGE - padding LARGE
__global__ void __launch_bounds__(256) k_logits(
    const int* __restrict__ qmask,
    const int* __restrict__ smask)
{
    __shared__ float sA[16 * 64];
    __shared__ float sB[2176];      // phase A: key tile (16x64); phase B: S band 127 rows x 17 (padded)

    int tid = threadIdx.x;
    int tx = tid & 15, ty = tid >> 4;
    int kv0 = blockIdx.x * 64;
    int qt0 = blockIdx.y * 64;
    int z = blockIdx.z;
    int b = z >> 3, h = z & 7;
    int am = tid >> 2, ak = (tid & 3) * 4;

    float acc[4][4];
#pragma unroll
    for (int i = 0; i < 4; i++)
#pragma unroll
        for (int j = 0; j < 4; j++) acc[i][j] = 0.f;

    // ---- phase A: content term, K = U = 64 ----
    const float* Qb = g_query + (size_t)(b * TT) * (HH * UU) + h * UU;
    const float* Kb = g_key   + (size_t)(b * KVL) * (HH * UU) + h * UU;
    for (int k0 = 0; k0 < UU; k0 += 16) {
        float4 qa = *(const float4*)(Qb + (size_t)(qt0 + am) * (HH * UU) + (k0 + ak));
        float4 ka = *(const float4*)(Kb + (size_t)(kv0 + am) * (HH * UU) + (k0 + ak));
        __syncthreads();
        sA[(ak + 0) * 64 + am] = qa.x;
        sA[(ak + 1) * 64 + am] = qa.y;
        sA[(ak + 2) * 64 + am] = qa.z;
        sA[(ak + 3) * 64 + am] = qa.w;
        sB[(ak + 0) * 64 + am] = ka.x;
        sB[(ak + 1) * 64 + am] = ka.y;
        sB[(ak + 2) * 64 + am] = ka.z;
        sB[(ak + 3) * 64 + am] = ka.w;
        __syncthreads();
#pragma unroll
        for (int kk = 0; kk < 16; kk++) {
            float4 a4 = *(const float4*)&sA[kk * 64 + ty * 4];
            float4 b4 = *(const float4*)&sB[kk * 64 + tx * 4];
            float a[4] = {a4.x, a4.y, a4.z, a4.w};
            float bb[4] = {b4.x, b4.y, b4.z, b4.w};
#pragma unroll
            for (int i = 0; i < 4; i++)
#pragma unroll
                for (int j = 0; j < 4; j++) acc[i][j] = fmaf(a[i], bb[j], acc[i][j]);
        }
    }

    // ---- phase B: banded position term, K = D = 512 ----
    // table row index = qt - kv + 1023 = rbase + relLocal; relLocal = 63 + (ty-tx)*4 + i - j
    const float* QVb = g_qv + (size_t)(b * TT) * (HH * DDim) + h * DDim;
    int rbase = qt0 - kv0 + 960;
    int rrow = (ty - tx) * 4 + 63;   // relLocal at i=j=0

    for (int k0 = 0; k0 < DDim; k0 += 16) {
        float4 qa = *(const float4*)(QVb + (size_t)(qt0 + am) * (HH * DDim) + (k0 + ak));
        // S band: 127 rows x 16 cols = 508 float4 groups; two rounds of 256 threads
        int r0 = tid >> 2, kq0 = (tid & 3) * 4;
        float4 s0 = *(const float4*)(g_S + (size_t)(rbase + r0) * DDim + k0 + kq0);
        int idx1 = tid + 256;
        int r1 = idx1 >> 2, kq1 = (idx1 & 3) * 4;
        float4 s1 = make_float4(0.f, 0.f, 0.f, 0.f);
        bool has1 = (idx1 < 508);
        if (has1) s1 = *(const float4*)(g_S + (size_t)(rbase + r1) * DDim + k0 + kq1);
        __syncthreads();
        sA[(ak + 0) * 64 + am] = qa.x;
        sA[(ak + 1) * 64 + am] = qa.y;
        sA[(ak + 2) * 64 + am] = qa.z;
        sA[(ak + 3) * 64 + am] = qa.w;
        sB[r0 * 17 + kq0 + 0] = s0.x;
        sB[r0 * 17 + kq0 + 1] = s0.y;
        sB[r0 * 17 + kq0 + 2] = s0.z;
        sB[r0 * 17 + kq0 + 3] = s0.w;
        if (has1) {
            sB[r1 * 17 + kq1 + 0] = s1.x;
            sB[r1 * 17 + kq1 + 1] = s1.y;
            sB[r1 * 17 + kq1 + 2] = s1.z;
            sB[r1 * 17 + kq1 + 3] = s1.w;
        }
        __syncthreads();
#pragma unroll
        for (int kk = 0; kk < 16; kk++) {
            float4 a4 = *(const float4*)&sA[kk * 64 + ty * 4];
            float a[4] = {a4.x, a4.y, a4.z, a4.w};
            float sv[7];
#pragma unroll
            for (int d = 0; d < 7; d++) sv[d] = sB[(rrow + d - 3) * 17 + kk];
#pragma unroll
            for (int i = 0; i < 4; i++)
#pragma unroll
                for (int j = 0; j < 4; j++) acc[i][j] = fmaf(a[i], sv[i - j + 3], acc[i][j]);
        }
    }

    // ---- epilogue: ubias, scale, masks ----
    float* Lb = g_logits + ((size_t)z * TT) * KVL;
#pragma unroll
    for (int i = 0; i < 4; i++) {
        int qt = qt0 + ty * 4 + i;
        float4 o;
        float vals[4];
#pragma unroll
        for (int j = 0; j < 4; j++) {
            int kv = kv0 + tx * 4 + j;
            float ub = g_ubias[(size_t)z * KVL + kv];
            float v = (acc[i][j] + ub) * 0.125f;
            if (kv - qt >= (KVL - TT + 1)) v -= LARGE_BIAS;   // causal triu, k = 513
            int cm = (kv < MMs) ? smask[b * MMs + kv]
                                : qmask[b * TT + (kv - MMs)];
            if (!cm) v -= LARGE_BIAS;                         // key padding
            vals[j] = v;
        }
        o.x = vals[0]; o.y = vals[1]; o.z = vals[2]; o.w = vals[3];
        *(float4*)&Lb[(size_t)qt * KVL + kv0 + tx * 4] = o;
    }
}

// ---------------- softmax over kv (in place on g_logits) ----------------
__global__ void __launch_bounds__(256) k_softmax() {
    float* row = g_logits + (size_t)blockIdx.x * KVL;
    int tid = threadIdx.x;
    int lane = tid & 31, wid = tid >> 5;
    __shared__ float red[8];
    __shared__ float bc;

    float v[4];
    float mx = -1e30f;
#pragma unroll
    for (int i = 0; i < 4; i++) {
        v[i] = row[tid + i * 256];
        mx = fmaxf(mx, v[i]);
    }
#pragma unroll
    for (int o = 16; o > 0; o >>= 1) mx = fmaxf(mx, __shfl_xor_sync(0xffffffff, mx, o));
    if (lane == 0) red[wid] = mx;
    __syncthreads();
    if (wid == 0) {
        float m2 = (lane < 8) ? red[lane] : -1e30f;
#pragma unroll
        for (int o = 16; o > 0; o >>= 1) m2 = fmaxf(m2, __shfl_xor_sync(0xffffffff, m2, o));
        if (lane == 0) bc = m2;
    }
    __syncthreads();
    mx = bc;

    float s = 0.f;
#pragma unroll
    for (int i = 0; i < 4; i++) {
        v[i] = expf(v[i] - mx);
        s += v[i];
    }
#pragma unroll
    for (int o = 16; o > 0; o >>= 1) s += __shfl_xor_sync(0xffffffff, s, o);
    __syncthreads();   // red[] reuse
    if (lane == 0) red[wid] = s;
    __syncthreads();
    if (wid == 0) {
        float s2 = (lane < 8) ? red[lane] : 0.f;
#pragma unroll
        for (int o = 16; o > 0; o >>= 1) s2 += __shfl_xor_sync(0xffffffff, s2, o);
        if (lane == 0) bc = s2;
    }
    __syncthreads();
    float inv = 1.f / bc;
#pragma unroll
    for (int i = 0; i < 4; i++) row[tid + i * 256] = v[i] * inv;
}

// ---------------- host launch ----------------
static float* symaddr(const void* sym) {
    void* p = 0;
    cudaGetSymbolAddress(&p, sym);
    return (float*)p;
}

extern "C" void kernel_launch(void* const* d_in, const int* in_sizes, int n_in,
                              void* d_out, int out_size) {
    (void)in_sizes; (void)n_in; (void)out_size;
    const float* inputs = (const float*)d_in[0];
    const float* state  = (const float*)d_in[1];
    const int* mask     = (const int*)d_in[2];    // bool inputs arrive as int32
    const int* smask    = (const int*)d_in[3];
    const float* qW     = (const float*)d_in[4];
    const float* kW     = (const float*)d_in[5];
    const float* rW     = (const float*)d_in[6];
    const float* vW     = (const float*)d_in[7];
    const float* uW     = (const float*)d_in[8];
    const float* vv     = (const float*)d_in[9];
    const float* oW     = (const float*)d_in[10];
    float* out = (float*)d_out;

    float* pConcat = symaddr(g_concat);
    float* pQuery  = symaddr(g_query);
    float* pKey    = symaddr(g_key);
    float* pValue  = symaddr(g_value);
    float* pRelT   = symaddr(g_relT);
    float* pVrel   = symaddr(g_vrel);
    float* pQv     = symaddr(g_qv);
    float* pLogits = symaddr(g_logits);
    float* pAtt    = symaddr(g_att);

    // prep
    k_tables<<<(NREL * DDim + 255) / 256, 256>>>();
    k_concat<<<(BB * KVL * DDim + 255) / 256, 256>>>(inputs, state);
    k_relT<<<(DDim * HH * UU + 255) / 256, 256>>>(rW);
    k_vrel<<<(HH * DDim + 255) / 256, 256>>>(vv, rW);

    // query = inputs @ qW, masked.  M=1024 N=512 K=512
    gemm64<<<dim3(8, 16, 1), 256>>>(inputs, qW, pQuery,
        512, 512, 512, 512,
        0, 0, 0,  0, 0, 0, 0, 0, 0,  1,
        mask, (const float*)0, 0, 0);

    // key / value = concat @ W.  M=2048 N=512 K=512
    gemm64<<<dim3(8, 32, 1), 256>>>(pConcat, kW, pKey,
        512, 512, 512, 512,
        0, 0, 0,  0, 0, 0, 0, 0, 0,  1,
        (const int*)0, (const float*)0, 0, 0);
    gemm64<<<dim3(8, 32, 1), 256>>>(pConcat, vW, pValue,
        512, 512, 512, 512,
        0, 0, 0,  0, 0, 0, 0, 0, 0,  1,
        (const int*)0, (const float*)0, 0, 0);

    // qv[b,t,h,:] = query_h @ relT_h + vrel_h.  per-h: M=1024 N=512 K=64
    gemm64<<<dim3(8, 16, HH), 256>>>(pQuery, pRelT, pQv,
        512, 512, 4096, 64,
        0, 0, 0,
        0, 64,               // A z2-stride: h*64
        0, (long)UU * DDim,  // B z2-stride: h*U*D
        0, 512,              // C z2-stride: h*512
        HH,
        (const int*)0, pVrel, 0, 512);

    k_ubias<<<(BB * HH * KVL + 255) / 256, 256>>>(uW);

    // fused logits (content + banded pos + bias + masks)
    k_logits<<<dim3(KVL / 64, TT / 64, BB * HH), 256>>>(mask, smask);

    // softmax over kv
    k_softmax<<<BB * HH * TT, 256>>>();

    // attended = weights @ value.  per-(b,h): M=512 N=64 K=1024
    gemm64<<<dim3(1, 8, BB * HH), 256>>>(pLogits, pValue, pAtt,
        KVL, 512, 512, KVL,
        0, 0, 0,
        (long)HH * TT * KVL, (long)TT * KVL,   // A: b, h strides
        (long)KVL * 512,     64,               // B (value): b, h strides
        (long)TT * 512,      64,               // C (att): b, h strides
        HH,
        (const int*)0, (const float*)0, 0, 0);

    // out = attended @ output_W.  M=1024 N=512 K=512
    gemm64<<<dim3(8, 16, 1), 256>>>(pAtt, oW, out,
        512, 512, 512, 512,
        0, 0, 0,  0, 0, 0, 0, 0, 0,  1,
        (const int*)0, (const float*)0, 0, 0);
}

// round 5
// speedup vs baseline: 1.1343x; 1.1343x over previous
#include <cuda_runtime.h>
#include <cuda_bf16.h>
#include <mma.h>
#include <math.h>

using namespace nvcuda;

#define BB 2
#define TT 512
#define MMs 512
#define DDim 512
#define HH 8
#define UU 64
#define KVL 1024
#define LARGE_BIAS 10000.0f

// ---------------- scratch (static device globals; no allocation) ----------------
__device__ __align__(128) float g_concat[BB * KVL * DDim];
__device__ __align__(128) float g_query[BB * TT * HH * UU];
__device__ __align__(128) float g_key[BB * KVL * HH * UU];
__device__ __align__(128) float g_value[BB * KVL * HH * UU];
__device__ __align__(128) float g_relT[HH * UU * DDim];
__device__ __align__(128) float g_vrel[HH * DDim];
__device__ __align__(128) float g_qv[BB * TT * HH * DDim];
__device__ __align__(128) float g_ubias[BB * HH * KVL];
__device__ __align__(128) float g_logits[BB * HH * TT * KVL];
__device__ __align__(128) float g_att[BB * TT * HH * UU];
// tensor-path operands
__device__ __align__(128) float2 g_qtrig[TT * DDim];                 // (sinAq, cosAq)
__device__ __align__(128) __nv_bfloat16 g_Ktrig_h[KVL * 1024];       // [kv][2d]=cosB,[2d+1]=sinB
__device__ __align__(128) __nv_bfloat16 g_Ktrig_l[KVL * 1024];
__device__ __align__(128) __nv_bfloat16 g_Bkey_h[16 * KVL * UU];
__device__ __align__(128) __nv_bfloat16 g_Bkey_l[16 * KVL * UU];
__device__ __align__(128) __nv_bfloat16 g_Acat_h[16 * TT * 1088];    // [bh][qt][64 q | 1024 pos]
__device__ __align__(128) __nv_bfloat16 g_Acat_l[16 * TT * 1088];

__device__ __forceinline__ void bsplit(float x, __nv_bfloat16& h, __nv_bfloat16& l) {
    h = __float2bfloat16(x);
    l = __float2bfloat16(x - __bfloat162float(h));
}

// ---------------- prep kernels ----------------
__global__ void k_concat(const float* __restrict__ in, const float* __restrict__ st) {
    int i = blockIdx.x * blockDim.x + threadIdx.x;
    if (i >= BB * KVL * DDim) return;
    int d = i & 511, j = (i >> 9) & 1023, b = i >> 19;
    g_concat[i] = (j < MMs) ? st[((size_t)(b * MMs + j)) * 512 + d]
                            : in[((size_t)(b * TT + (j - MMs))) * 512 + d];
}
__global__ void k_relT(const float* __restrict__ rW) {
    int i = blockIdx.x * blockDim.x + threadIdx.x;
    if (i >= DDim * 512) return;
    g_relT[(size_t)(i & 511) * 512 + (i >> 9)] = rW[i];
}
__global__ void k_vrel(const float* __restrict__ vv, const float* __restrict__ rW) {
    int g = (blockIdx.x * blockDim.x + threadIdx.x) >> 5, lane = threadIdx.x & 31;
    if (g >= HH * DDim) return;
    int h = g >> 9, d = g & 511;
    const float* rp = rW + (size_t)d * 512 + h * 64;
    const float* vp = vv + h * 64;
    float s = rp[lane] * vp[lane] + rp[lane + 32] * vp[lane + 32];
#pragma unroll
    for (int o = 16; o > 0; o >>= 1) s += __shfl_xor_sync(~0u, s, o);
    if (!lane) g_vrel[h * 512 + d] = s;
}
__global__ void k_ubias(const float* __restrict__ uW) {
    int i = blockIdx.x * blockDim.x + threadIdx.x;
    if (i >= BB * HH * KVL) return;
    int kv = i & 1023, h = (i >> 10) & 7, b = i >> 13;
    const float* kp = g_key + ((size_t)(b * KVL + kv)) * 512 + h * 64;
    const float* up = uW + h * 64;
    float s = 0.f;
#pragma unroll
    for (int u = 0; u < 64; u++) s = fmaf(kp[u], up[u], s);
    g_ubias[i] = s;
}
__global__ void k_qtrig() {
    int i = blockIdx.x * blockDim.x + threadIdx.x;
    if (i >= TT * DDim) return;
    int d = i & 511, qt = i >> 9;
    float invw = powf(10000.0f, -2.0f * (float)d / 512.0f);
    float off = (d & 1) ? 1.57079632679489662f : 0.0f;
    float s, c;
    sincosf((float)(qt + 512) * invw + off, &s, &c);
    g_qtrig[i] = make_float2(s, c);
}
__global__ void k_ktrig() {
    int i = blockIdx.x * blockDim.x + threadIdx.x;
    if (i >= KVL * DDim) return;
    int d = i & 511, kv = i >> 9;
    float invw = powf(10000.0f, -2.0f * (float)d / 512.0f);
    float s, c;
    sincosf((float)kv * invw, &s, &c);
    __nv_bfloat16 ch, cl, sh, sl;
    bsplit(c, ch, cl);
    bsplit(s, sh, sl);
    __nv_bfloat162 vh, vl;
    vh.x = ch; vh.y = sh; vl.x = cl; vl.y = sl;
    *(__nv_bfloat162*)&g_Ktrig_h[(size_t)kv * 1024 + 2 * d] = vh;
    *(__nv_bfloat162*)&g_Ktrig_l[(size_t)kv * 1024 + 2 * d] = vl;
}
__global__ void k_bkey() {
    int i = blockIdx.x * blockDim.x + threadIdx.x;
    if (i >= 16 * KVL * UU) return;
    int u = i & 63, kv = (i >> 6) & 1023, bh = i >> 16;
    int b = bh >> 3, h = bh & 7;
    __nv_bfloat16 hi, lo;
    bsplit(g_key[(size_t)(b * KVL + kv) * 512 + h * 64 + u], hi, lo);
    g_Bkey_h[i] = hi;
    g_Bkey_l[i] = lo;
}
__global__ void k_acat_c() {   // content cols 0..63
    int i = blockIdx.x * blockDim.x + threadIdx.x;
    if (i >= 16 * TT * UU) return;
    int u = i & 63, qt = (i >> 6) & 511, bh = i >> 15;
    int b = bh >> 3, h = bh & 7;
    __nv_bfloat16 hi, lo;
    bsplit(g_query[(size_t)(b * TT + qt) * 512 + h * 64 + u], hi, lo);
    size_t o = ((size_t)bh * TT + qt) * 1088 + u;
    g_Acat_h[o] = hi;
    g_Acat_l[o] = lo;
}
__global__ void k_acat_p() {   // pos cols 64+2d (qv*sinAq), 64+2d+1 (-qv*cosAq)
    int i = blockIdx.x * blockDim.x + threadIdx.x;
    if (i >= 16 * TT * DDim) return;
    int d = i & 511, qt = (i >> 9) & 511, bh = i >> 18;
    int b = bh >> 3, h = bh & 7;
    float q = g_qv[(size_t)(b * TT + qt) * 4096 + h * 512 + d];
    float2 tr = g_qtrig[qt * 512 + d];
    __nv_bfloat16 sh, sl, ch, cl;
    bsplit(q * tr.x, sh, sl);
    bsplit(-q * tr.y, ch, cl);
    size_t o = ((size_t)bh * TT + qt) * 1088 + 64 + 2 * d;
    __nv_bfloat162 vh, vl;
    vh.x = sh; vh.y = ch; vl.x = sl; vl.y = cl;
    *(__nv_bfloat162*)&g_Acat_h[o] = vh;
    *(__nv_bfloat162*)&g_Acat_l[o] = vl;
}

// ---------------- generic fp32 tiled GEMM (known-good) ----------------
__global__ void __launch_bounds__(256) gemm64(
    const float* __restrict__ A, const float* __restrict__ Bm, float* __restrict__ C,
    int lda, int ldbk, int ldc, int Kdim,
    long az1, long az2, long bz1, long bz2, long cz1, long cz2, int Z2,
    const int* __restrict__ rowmask, const float* __restrict__ bias, long biasz2)
{
    __shared__ float sA[16 * 64];
    __shared__ float sB[16 * 64];
    int z = blockIdx.z, z1 = z / Z2, z2 = z - z1 * Z2;
    const float* Ap = A + (size_t)z1 * az1 + (size_t)z2 * az2;
    const float* Bp = Bm + (size_t)z1 * bz1 + (size_t)z2 * bz2;
    float* Cp = C + (size_t)z1 * cz1 + (size_t)z2 * cz2;
    const float* biasp = bias ? (bias + (size_t)z2 * biasz2) : (const float*)0;
    int m0 = blockIdx.y * 64, n0 = blockIdx.x * 64, tid = threadIdx.x;
    int tx = tid & 15, ty = tid >> 4;
    int am = tid >> 2, ak = (tid & 3) * 4, bk = tid >> 4, bn = (tid & 15) * 4;
    float acc[4][4] = {};
    for (int k0 = 0; k0 < Kdim; k0 += 16) {
        float4 av = *(const float4*)(Ap + (size_t)(m0 + am) * lda + (k0 + ak));
        float4 bv = *(const float4*)(Bp + (size_t)(k0 + bk) * ldbk + (n0 + bn));
        __syncthreads();
        sA[(ak + 0) * 64 + am] = av.x; sA[(ak + 1) * 64 + am] = av.y;
        sA[(ak + 2) * 64 + am] = av.z; sA[(ak + 3) * 64 + am] = av.w;
        *(float4*)&sB[bk * 64 + bn] = bv;
        __syncthreads();
#pragma unroll
        for (int kk = 0; kk < 16; kk++) {
            float4 a4 = *(const float4*)&sA[kk * 64 + ty * 4];
            float4 b4 = *(const float4*)&sB[kk * 64 + tx * 4];
            float a[4] = {a4.x, a4.y, a4.z, a4.w}, bb[4] = {b4.x, b4.y, b4.z, b4.w};
#pragma unroll
            for (int i = 0; i < 4; i++)
#pragma unroll
                for (int j = 0; j < 4; j++) acc[i][j] = fmaf(a[i], bb[j], acc[i][j]);
        }
    }
#pragma unroll
    for (int i = 0; i < 4; i++) {
        int mg = m0 + ty * 4 + i;
        float sc = rowmask ? (rowmask[mg] ? 1.f : 0.f) : 1.f;
        float4 o;
        float v[4];
#pragma unroll
        for (int j = 0; j < 4; j++) {
            float x = acc[i][j];
            if (biasp) x += biasp[n0 + tx * 4 + j];
            v[j] = x * sc;
        }
        o.x = v[0]; o.y = v[1]; o.z = v[2]; o.w = v[3];
        *(float4*)&Cp[(size_t)mg * ldc + n0 + tx * 4] = o;
    }
}

// ---------------- WMMA logits: per (b,h) C[512,1024] = Acat @ Bcat^T, K=1088, 3-pass hi/lo ----------------
#define PADA 40
#define OUTLD 20

__global__ void __launch_bounds__(256, 1) k_logits_wmma(
    const int* __restrict__ qmask, const int* __restrict__ smask)
{
    __shared__ __nv_bfloat16 sAh[128 * PADA];
    __shared__ __nv_bfloat16 sAl[128 * PADA];
    __shared__ __nv_bfloat16 sBh[128 * PADA];
    __shared__ __nv_bfloat16 sBl[128 * PADA];

    int tid = threadIdx.x, wid = tid >> 5, lane = tid & 31;
    int kv0 = blockIdx.x * 128, qt0 = blockIdx.y * 128, bh = blockIdx.z;
    int b = bh >> 3;
    int wy = wid >> 2, wx = wid & 3;   // warp tile: rows [wy*64,+64), cols [wx*32,+32)

    wmma::fragment<wmma::accumulator, 16, 16, 16, float> acc[4][2];
#pragma unroll
    for (int mi = 0; mi < 4; mi++)
#pragma unroll
        for (int ni = 0; ni < 2; ni++) wmma::fill_fragment(acc[mi][ni], 0.f);

    const __nv_bfloat16* Ah = g_Acat_h + ((size_t)bh * TT + qt0) * 1088;
    const __nv_bfloat16* Al = g_Acat_l + ((size_t)bh * TT + qt0) * 1088;

    for (int kc = 0; kc < 34; kc++) {     // K chunks of 32 over 1088
        const __nv_bfloat16 *Bhp, *Blp;
        int bld, bcol;
        if (kc < 2) {
            Bhp = g_Bkey_h + (size_t)bh * KVL * 64;
            Blp = g_Bkey_l + (size_t)bh * KVL * 64;
            bld = 64; bcol = kc * 32;
        } else {
            Bhp = g_Ktrig_h; Blp = g_Ktrig_l;
            bld = 1024; bcol = (kc - 2) * 32;
        }
        __syncthreads();
#pragma unroll
        for (int t = tid; t < 512; t += 256) {
            int row = t >> 2, seg = (t & 3) * 8;
            *(uint4*)&sAh[row * PADA + seg] = *(const uint4*)(Ah + (size_t)row * 1088 + kc * 32 + seg);
            *(uint4*)&sAl[row * PADA + seg] = *(const uint4*)(Al + (size_t)row * 1088 + kc * 32 + seg);
            *(uint4*)&sBh[row * PADA + seg] = *(const uint4*)(Bhp + (size_t)(kv0 + row) * bld + bcol + seg);
            *(uint4*)&sBl[row * PADA + seg] = *(const uint4*)(Blp + (size_t)(kv0 + row) * bld + bcol + seg);
        }
        __syncthreads();
#pragma unroll
        for (int ks = 0; ks < 2; ks++) {
            wmma::fragment<wmma::matrix_a, 16, 16, 16, __nv_bfloat16, wmma::row_major> fah[4], fal[4];
            wmma::fragment<wmma::matrix_b, 16, 16, 16, __nv_bfloat16, wmma::col_major> fbh[2], fbl[2];
#pragma unroll
            for (int mi = 0; mi < 4; mi++) {
                wmma::load_matrix_sync(fah[mi], &sAh[(wy * 64 + mi * 16) * PADA + ks * 16], PADA);
                wmma::load_matrix_sync(fal[mi], &sAl[(wy * 64 + mi * 16) * PADA + ks * 16], PADA);
            }
#pragma unroll
            for (int ni = 0; ni < 2; ni++) {
                wmma::load_matrix_sync(fbh[ni], &sBh[(wx * 32 + ni * 16) * PADA + ks * 16], PADA);
                wmma::load_matrix_sync(fbl[ni], &sBl[(wx * 32 + ni * 16) * PADA + ks * 16], PADA);
            }
#pragma unroll
            for (int mi = 0; mi < 4; mi++)
#pragma unroll
                for (int ni = 0; ni < 2; ni++) {
                    wmma::mma_sync(acc[mi][ni], fah[mi], fbh[ni], acc[mi][ni]);
                    wmma::mma_sync(acc[mi][ni], fah[mi], fbl[ni], acc[mi][ni]);
                    wmma::mma_sync(acc[mi][ni], fal[mi], fbh[ni], acc[mi][ni]);
                }
        }
    }

    // epilogue: alias sAh as per-warp float staging (8 warps x 16x20 floats = 10240 B <= 10240 B)
    __syncthreads();
    float* sOut = (float*)sAh + wid * 16 * OUTLD;
    const float* ub = g_ubias + (size_t)bh * KVL;
#pragma unroll
    for (int mi = 0; mi < 4; mi++)
#pragma unroll
        for (int ni = 0; ni < 2; ni++) {
            wmma::store_matrix_sync(sOut, acc[mi][ni], OUTLD, wmma::mem_row_major);
            __syncwarp();
#pragma unroll
            for (int e = 0; e < 8; e++) {
                int idx = lane * 8 + e;       // 0..255
                int r = idx >> 4, c = idx & 15;
                int qt = qt0 + wy * 64 + mi * 16 + r;
                int kv = kv0 + wx * 32 + ni * 16 + c;
                float x = (sOut[r * OUTLD + c] + ub[kv]) * 0.125f;
                if (kv - qt >= 513) x -= LARGE_BIAS;
                int cm = (kv < MMs) ? smask[b * MMs + kv] : qmask[b * TT + (kv - MMs)];
                if (!cm) x -= LARGE_BIAS;
                g_logits[((size_t)bh * TT + qt) * KVL + kv] = x;
            }
            __syncwarp();
        }
}

// ---------------- softmax ----------------
__global__ void __launch_bounds__(256) k_softmax() {
    float* row = g_logits + (size_t)blockIdx.x * KVL;
    int tid = threadIdx.x, lane = tid & 31, wid = tid >> 5;
    __shared__ float red[8];
    __shared__ float bc;
    float v[4], mx = -1e30f;
#pragma unroll
    for (int i = 0; i < 4; i++) { v[i] = row[tid + i * 256]; mx = fmaxf(mx, v[i]); }
#pragma unroll
    for (int o = 16; o > 0; o >>= 1) mx = fmaxf(mx, __shfl_xor_sync(~0u, mx, o));
    if (!lane) red[wid] = mx;
    __syncthreads();
    if (!wid) {
        float m2 = (lane < 8) ? red[lane] : -1e30f;
#pragma unroll
        for (int o = 16; o > 0; o >>= 1) m2 = fmaxf(m2, __shfl_xor_sync(~0u, m2, o));
        if (!lane) bc = m2;
    }
    __syncthreads();
    mx = bc;
    float s = 0.f;
#pragma unroll
    for (int i = 0; i < 4; i++) { v[i] = expf(v[i] - mx); s += v[i]; }
#pragma unroll
    for (int o = 16; o > 0; o >>= 1) s += __shfl_xor_sync(~0u, s, o);
    __syncthreads();
    if (!lane) red[wid] = s;
    __syncthreads();
    if (!wid) {
        float s2 = (lane < 8) ? red[lane] : 0.f;
#pragma unroll
        for (int o = 16; o > 0; o >>= 1) s2 += __shfl_xor_sync(~0u, s2, o);
        if (!lane) bc = s2;
    }
    __syncthreads();
    float inv = 1.f / bc;
#pragma unroll
    for (int i = 0; i < 4; i++) row[tid + i * 256] = v[i] * inv;
}

// ---------------- host ----------------
static float* symaddr(const void* s) { void* p = 0; cudaGetSymbolAddress(&p, s); return (float*)p; }

extern "C" void kernel_launch(void* const* d_in, const int* in_sizes, int n_in,
                              void* d_out, int out_size) {
    (void)in_sizes; (void)n_in; (void)out_size;
    const float* inputs = (const float*)d_in[0];
    const float* state  = (const float*)d_in[1];
    const int* mask     = (const int*)d_in[2];
    const int* smask    = (const int*)d_in[3];
    const float* qW = (const float*)d_in[4];
    const float* kW = (const float*)d_in[5];
    const float* rW = (const float*)d_in[6];
    const float* vW = (const float*)d_in[7];
    const float* uW = (const float*)d_in[8];
    const float* vv = (const float*)d_in[9];
    const float* oW = (const float*)d_in[10];
    float* out = (float*)d_out;

    float* pConcat = symaddr(g_concat);
    float* pQuery  = symaddr(g_query);
    float* pKey    = symaddr(g_key);
    float* pValue  = symaddr(g_value);
    float* pRelT   = symaddr(g_relT);
    float* pVrel   = symaddr(g_vrel);
    float* pQv     = symaddr(g_qv);
    float* pLogits = symaddr(g_logits);
    float* pAtt    = symaddr(g_att);

    k_concat<<<(BB * KVL * DDim + 255) / 256, 256>>>(inputs, state);
    k_relT<<<(DDim * 512 + 255) / 256, 256>>>(rW);
    k_vrel<<<(HH * DDim * 32 + 255) / 256, 256>>>(vv, rW);
    k_qtrig<<<(TT * DDim + 255) / 256, 256>>>();
    k_ktrig<<<(KVL * DDim + 255) / 256, 256>>>();

    // query = inputs @ qW (masked)
    gemm64<<<dim3(8, 16, 1), 256>>>(inputs, qW, pQuery, 512, 512, 512, 512,
        0, 0, 0, 0, 0, 0, 1, mask, (const float*)0, 0);
    // key / value
    gemm64<<<dim3(8, 32, 1), 256>>>(pConcat, kW, pKey, 512, 512, 512, 512,
        0, 0, 0, 0, 0, 0, 1, (const int*)0, (const float*)0, 0);
    gemm64<<<dim3(8, 32, 1), 256>>>(pConcat, vW, pValue, 512, 512, 512, 512,
        0, 0, 0, 0, 0, 0, 1, (const int*)0, (const float*)0, 0);
    // qv per-head: qv = query_h @ relT_h + vrel_h
    gemm64<<<dim3(8, 16, HH), 256>>>(pQuery, pRelT, pQv, 512, 512, 4096, 64,
        0, 64, 0, (long)UU * DDim, 0, 512, HH, (const int*)0, pVrel, 512);

    k_ubias<<<(BB * HH * KVL + 255) / 256, 256>>>(uW);
    k_bkey<<<(16 * KVL * UU + 255) / 256, 256>>>();
    k_acat_c<<<(16 * TT * UU + 255) / 256, 256>>>();
    k_acat_p<<<(16 * TT * DDim + 255) / 256, 256>>>();

    // logits on tensor cores (WMMA bf16 3-pass)
    k_logits_wmma<<<dim3(KVL / 128, TT / 128, 16), 256>>>(mask, smask);

    k_softmax<<<BB * HH * TT, 256>>>();

    // attended = weights @ value
    gemm64<<<dim3(1, 8, 16), 256>>>(pLogits, pValue, pAtt, KVL, 512, 512, KVL,
        (long)HH * TT * KVL, (long)TT * KVL,
        (long)KVL * 512, 64, (long)TT * 512, 64, HH,
        (const int*)0, (const float*)0, 0);
    // out = attended @ output_W
    gemm64<<<dim3(8, 16, 1), 256>>>(pAtt, oW, out, 512, 512, 512, 512,
        0, 0, 0, 0, 0, 0, 1, (const int*)0, (const float*)0, 0);
}

// round 7
// speedup vs baseline: 1.3050x; 1.1504x over previous
#include <cuda_runtime.h>
#include <cuda_bf16.h>
#include <mma.h>
#include <math.h>

using namespace nvcuda;

#define BB 2
#define TT 512
#define MMs 512
#define DDim 512
#define HH 8
#define UU 64
#define KVL 1024
#define LARGE_BIAS 10000.0f

// ---------------- scratch (static device globals; no allocation) ----------------
__device__ __align__(128) float g_query[BB * TT * HH * UU];
__device__ __align__(128) float g_key[BB * KVL * HH * UU];
__device__ __align__(128) float g_value[BB * KVL * HH * UU];
__device__ __align__(128) float g_vrel[HH * DDim];
__device__ __align__(128) float g_qv[BB * TT * HH * DDim];
__device__ __align__(128) float g_ubias[BB * HH * KVL];
__device__ __align__(128) float g_logits[BB * HH * TT * KVL];
__device__ __align__(128) float g_att[BB * TT * HH * UU];
__device__ __align__(128) float2 g_qtrig[TT * DDim];
// bf16 hi/lo operand pools
__device__ __align__(128) __nv_bfloat16 g_inh[TT * BB * DDim],  g_inl[TT * BB * DDim];
__device__ __align__(128) __nv_bfloat16 g_conh[BB * KVL * DDim], g_conl[BB * KVL * DDim];
__device__ __align__(128) __nv_bfloat16 g_qWh[DDim * 512], g_qWl[DDim * 512];
__device__ __align__(128) __nv_bfloat16 g_kWh[DDim * 512], g_kWl[DDim * 512];
__device__ __align__(128) __nv_bfloat16 g_vWh[DDim * 512], g_vWl[DDim * 512];
__device__ __align__(128) __nv_bfloat16 g_oWh[HH * UU * 512], g_oWl[HH * UU * 512];
__device__ __align__(128) __nv_bfloat16 g_relh[HH * UU * DDim], g_rell[HH * UU * DDim];
__device__ __align__(128) __nv_bfloat16 g_qh[BB * TT * 512], g_ql[BB * TT * 512];
__device__ __align__(128) __nv_bfloat16 g_valh[BB * KVL * 512], g_vall[BB * KVL * 512];
__device__ __align__(128) __nv_bfloat16 g_atth[BB * TT * 512], g_attl[BB * TT * 512];
__device__ __align__(128) __nv_bfloat16 g_Wh[16 * TT * KVL], g_Wl[16 * TT * KVL];
// logits tensor-path operands
__device__ __align__(128) __nv_bfloat16 g_Ktrig_h[KVL * 1024], g_Ktrig_l[KVL * 1024];
__device__ __align__(128) __nv_bfloat16 g_Bkey_h[16 * KVL * UU], g_Bkey_l[16 * KVL * UU];
__device__ __align__(128) __nv_bfloat16 g_Acat_h[16 * TT * 1088], g_Acat_l[16 * TT * 1088];

__device__ __forceinline__ void bsplit(float x, __nv_bfloat16& h, __nv_bfloat16& l) {
    h = __float2bfloat16(x);
    l = __float2bfloat16(x - __bfloat162float(h));
}

// ---------------- elementwise prep ----------------
__global__ void k_split(const float* __restrict__ s, __nv_bfloat16* __restrict__ h,
                        __nv_bfloat16* __restrict__ l, int n) {
    int i = blockIdx.x * blockDim.x + threadIdx.x;
    if (i >= n) return;
    __nv_bfloat16 hi, lo;
    bsplit(s[i], hi, lo);
    h[i] = hi; l[i] = lo;
}
__global__ void k_concat(const float* __restrict__ in, const float* __restrict__ st) {
    int i = blockIdx.x * blockDim.x + threadIdx.x;
    if (i >= BB * KVL * DDim) return;
    int d = i & 511, j = (i >> 9) & 1023, b = i >> 19;
    float v = (j < MMs) ? st[((size_t)(b * MMs + j)) * 512 + d]
                        : in[((size_t)(b * TT + (j - MMs))) * 512 + d];
    __nv_bfloat16 hi, lo;
    bsplit(v, hi, lo);
    g_conh[i] = hi; g_conl[i] = lo;
}
__global__ void k_relT(const float* __restrict__ rW) {
    int i = blockIdx.x * blockDim.x + threadIdx.x;
    if (i >= DDim * 512) return;
    __nv_bfloat16 hi, lo;
    bsplit(rW[i], hi, lo);
    size_t o = (size_t)(i & 511) * 512 + (i >> 9);
    g_relh[o] = hi; g_rell[o] = lo;
}
__global__ void k_vrel(const float* __restrict__ vv, const float* __restrict__ rW) {
    int g = (blockIdx.x * blockDim.x + threadIdx.x) >> 5, lane = threadIdx.x & 31;
    if (g >= HH * DDim) return;
    int h = g >> 9, d = g & 511;
    const float* rp = rW + (size_t)d * 512 + h * 64;
    const float* vp = vv + h * 64;
    float s = rp[lane] * vp[lane] + rp[lane + 32] * vp[lane + 32];
#pragma unroll
    for (int o = 16; o > 0; o >>= 1) s += __shfl_xor_sync(~0u, s, o);
    if (!lane) g_vrel[h * 512 + d] = s;
}
__global__ void k_ubias(const float* __restrict__ uW) {
    int i = blockIdx.x * blockDim.x + threadIdx.x;
    if (i >= BB * HH * KVL) return;
    int kv = i & 1023, h = (i >> 10) & 7, b = i >> 13;
    const float* kp = g_key + ((size_t)(b * KVL + kv)) * 512 + h * 64;
    const float* up = uW + h * 64;
    float s = 0.f;
#pragma unroll
    for (int u = 0; u < 64; u++) s = fmaf(kp[u], up[u], s);
    g_ubias[i] = s;
}
__global__ void k_qtrig() {
    int i = blockIdx.x * blockDim.x + threadIdx.x;
    if (i >= TT * DDim) return;
    int d = i & 511, qt = i >> 9;
    float invw = powf(10000.0f, -2.0f * (float)d / 512.0f);
    float off = (d & 1) ? 1.57079632679489662f : 0.0f;
    float s, c;
    sincosf((float)(qt + 512) * invw + off, &s, &c);
    g_qtrig[i] = make_float2(s, c);
}
__global__ void k_ktrig() {
    int i = blockIdx.x * blockDim.x + threadIdx.x;
    if (i >= KVL * DDim) return;
    int d = i & 511, kv = i >> 9;
    float invw = powf(10000.0f, -2.0f * (float)d / 512.0f);
    float s, c;
    sincosf((float)kv * invw, &s, &c);
    __nv_bfloat16 ch, cl, sh, sl;
    bsplit(c, ch, cl);
    bsplit(s, sh, sl);
    __nv_bfloat162 vh, vl;
    vh.x = ch; vh.y = sh; vl.x = cl; vl.y = sl;
    *(__nv_bfloat162*)&g_Ktrig_h[(size_t)kv * 1024 + 2 * d] = vh;
    *(__nv_bfloat162*)&g_Ktrig_l[(size_t)kv * 1024 + 2 * d] = vl;
}
__global__ void k_bkey() {
    int i = blockIdx.x * blockDim.x + threadIdx.x;
    if (i >= 16 * KVL * UU) return;
    int u = i & 63, kv = (i >> 6) & 1023, bh = i >> 16;
    int b = bh >> 3, h = bh & 7;
    __nv_bfloat16 hi, lo;
    bsplit(g_key[(size_t)(b * KVL + kv) * 512 + h * 64 + u], hi, lo);
    g_Bkey_h[i] = hi; g_Bkey_l[i] = lo;
}
__global__ void k_acat_c() {
    int i = blockIdx.x * blockDim.x + threadIdx.x;
    if (i >= 16 * TT * UU) return;
    int u = i & 63, qt = (i >> 6) & 511, bh = i >> 15;
    int b = bh >> 3, h = bh & 7;
    __nv_bfloat16 hi, lo;
    bsplit(g_query[(size_t)(b * TT + qt) * 512 + h * 64 + u], hi, lo);
    size_t o = ((size_t)bh * TT + qt) * 1088 + u;
    g_Acat_h[o] = hi; g_Acat_l[o] = lo;
}
__global__ void k_acat_p() {
    int i = blockIdx.x * blockDim.x + threadIdx.x;
    if (i >= 16 * TT * DDim) return;
    int d = i & 511, qt = (i >> 9) & 511, bh = i >> 18;
    int b = bh >> 3, h = bh & 7;
    float q = g_qv[(size_t)(b * TT + qt) * 4096 + h * 512 + d];
    float2 tr = g_qtrig[qt * 512 + d];
    __nv_bfloat16 sh, sl, ch, cl;
    bsplit(q * tr.x, sh, sl);
    bsplit(-q * tr.y, ch, cl);
    size_t o = ((size_t)bh * TT + qt) * 1088 + 64 + 2 * d;
    __nv_bfloat162 vh, vl;
    vh.x = sh; vh.y = ch; vl.x = sl; vl.y = cl;
    *(__nv_bfloat162*)&g_Acat_h[o] = vh;
    *(__nv_bfloat162*)&g_Acat_l[o] = vl;
}

// ---------------- generic WMMA hi/lo GEMM: C(f32) = A @ B, A row-major, B row-major ----------------
// tile 128(M) x 64(N), 8 warps (4x2), K chunks of 32, 3-pass (AhBh + AhBl + AlBh)
#define PADA 40
#define PADB 72
#define OUTLD 20

__global__ void __launch_bounds__(256) gemmw(
    const __nv_bfloat16* __restrict__ Ah, const __nv_bfloat16* __restrict__ Al,
    const __nv_bfloat16* __restrict__ Bh, const __nv_bfloat16* __restrict__ Bl,
    float* __restrict__ C,
    int lda, int ldb, int ldc, int Kdim,
    long az1, long az2, long bz1, long bz2, long cz1, long cz2, int Z2,
    const int* __restrict__ rowmask, const float* __restrict__ bias, long biasz2,
    int causal)
{
    __shared__ __nv_bfloat16 sAh[128 * PADA];
    __shared__ __nv_bfloat16 sAl[128 * PADA];
    __shared__ __nv_bfloat16 sBh[32 * PADB];
    __shared__ __nv_bfloat16 sBl[32 * PADB];

    int z = blockIdx.z, z1 = z / Z2, z2 = z - z1 * Z2;
    const __nv_bfloat16* Ahp = Ah + (size_t)z1 * az1 + (size_t)z2 * az2;
    const __nv_bfloat16* Alp = Al + (size_t)z1 * az1 + (size_t)z2 * az2;
    const __nv_bfloat16* Bhp = Bh + (size_t)z1 * bz1 + (size_t)z2 * bz2;
    const __nv_bfloat16* Blp = Bl + (size_t)z1 * bz1 + (size_t)z2 * bz2;
    float* Cp = C + (size_t)z1 * cz1 + (size_t)z2 * cz2;
    const float* biasp = bias ? (bias + (size_t)z2 * biasz2) : (const float*)0;

    int m0 = blockIdx.y * 128, n0 = blockIdx.x * 64;
    int tid = threadIdx.x, wid = tid >> 5, lane = tid & 31;
    int wy = wid >> 1, wx = wid & 1;          // warp tile rows [wy*32,+32), cols [wx*32,+32)

    wmma::fragment<wmma::accumulator, 16, 16, 16, float> acc[2][2];
#pragma unroll
    for (int mi = 0; mi < 2; mi++)
#pragma unroll
        for (int ni = 0; ni < 2; ni++) wmma::fill_fragment(acc[mi][ni], 0.f);

    int Klim = Kdim;
    if (causal) {
        int km = m0 + 640;                    // weights zero for kv >= qt+513
        Klim = (km < Kdim) ? ((km + 31) & ~31) : Kdim;
    }

    int arow = tid >> 1, asg = (tid & 1) * 16;
    int brow = tid >> 3, bsg = (tid & 7) * 8;

    for (int kc = 0; kc < Klim; kc += 32) {
        __syncthreads();
        *(uint4*)&sAh[arow * PADA + asg]     = *(const uint4*)(Ahp + (size_t)(m0 + arow) * lda + kc + asg);
        *(uint4*)&sAh[arow * PADA + asg + 8] = *(const uint4*)(Ahp + (size_t)(m0 + arow) * lda + kc + asg + 8);
        *(uint4*)&sAl[arow * PADA + asg]     = *(const uint4*)(Alp + (size_t)(m0 + arow) * lda + kc + asg);
        *(uint4*)&sAl[arow * PADA + asg + 8] = *(const uint4*)(Alp + (size_t)(m0 + arow) * lda + kc + asg + 8);
        *(uint4*)&sBh[brow * PADB + bsg]     = *(const uint4*)(Bhp + (size_t)(kc + brow) * ldb + n0 + bsg);
        *(uint4*)&sBl[brow * PADB + bsg]     = *(const uint4*)(Blp + (size_t)(kc + brow) * ldb + n0 + bsg);
        __syncthreads();
#pragma unroll
        for (int ks = 0; ks < 2; ks++) {
            wmma::fragment<wmma::matrix_a, 16, 16, 16, __nv_bfloat16, wmma::row_major> fah[2], fal[2];
            wmma::fragment<wmma::matrix_b, 16, 16, 16, __nv_bfloat16, wmma::row_major> fbh[2], fbl[2];
#pragma unroll
            for (int mi = 0; mi < 2; mi++) {
                wmma::load_matrix_sync(fah[mi], &sAh[(wy * 32 + mi * 16) * PADA + ks * 16], PADA);
                wmma::load_matrix_sync(fal[mi], &sAl[(wy * 32 + mi * 16) * PADA + ks * 16], PADA);
            }
#pragma unroll
            for (int ni = 0; ni < 2; ni++) {
                wmma::load_matrix_sync(fbh[ni], &sBh[ks * 16 * PADB + wx * 32 + ni * 16], PADB);
                wmma::load_matrix_sync(fbl[ni], &sBl[ks * 16 * PADB + wx * 32 + ni * 16], PADB);
            }
#pragma unroll
            for (int mi = 0; mi < 2; mi++)
#pragma unroll
                for (int ni = 0; ni < 2; ni++) {
                    wmma::mma_sync(acc[mi][ni], fah[mi], fbh[ni], acc[mi][ni]);
                    wmma::mma_sync(acc[mi][ni], fah[mi], fbl[ni], acc[mi][ni]);
                    wmma::mma_sync(acc[mi][ni], fal[mi], fbh[ni], acc[mi][ni]);
                }
        }
    }

    // epilogue via per-warp smem staging (alias sAh: 8 warps x 16x20 f32 = 10240B)
    __syncthreads();
    float* sOut = (float*)sAh + wid * 16 * OUTLD;
#pragma unroll
    for (int mi = 0; mi < 2; mi++)
#pragma unroll
        for (int ni = 0; ni < 2; ni++) {
            wmma::store_matrix_sync(sOut, acc[mi][ni], OUTLD, wmma::mem_row_major);
            __syncwarp();
#pragma unroll
            for (int e = 0; e < 8; e++) {
                int idx = lane * 8 + e;
                int r = idx >> 4, c = idx & 15;
                int mg = m0 + wy * 32 + mi * 16 + r;
                int ng = n0 + wx * 32 + ni * 16 + c;
                float x = sOut[r * OUTLD + c];
                if (biasp) x += biasp[ng];
                if (rowmask) x *= rowmask[mg] ? 1.f : 0.f;
                Cp[(size_t)mg * ldc + ng] = x;
            }
            __syncwarp();
        }
}

// ---------------- WMMA logits: per (b,h) C[512,1024] = Acat @ Bcat^T, K=1088, 3-pass ----------------
__global__ void __launch_bounds__(256, 1) k_logits_wmma(
    const int* __restrict__ qmask, const int* __restrict__ smask)
{
    __shared__ __nv_bfloat16 sAh[128 * PADA];
    __shared__ __nv_bfloat16 sAl[128 * PADA];
    __shared__ __nv_bfloat16 sBh[128 * PADA];
    __shared__ __nv_bfloat16 sBl[128 * PADA];

    int tid = threadIdx.x, wid = tid >> 5, lane = tid & 31;
    int kv0 = blockIdx.x * 128, qt0 = blockIdx.y * 128, bh = blockIdx.z;
    int b = bh >> 3;

    // fully causal-masked tile: weights will be exactly 0; write -LARGE and skip
    if (kv0 >= qt0 + 640) {
        float4 neg = make_float4(-LARGE_BIAS, -LARGE_BIAS, -LARGE_BIAS, -LARGE_BIAS);
        for (int t = tid; t < 128 * 32; t += 256) {
            int r = t >> 5, c = (t & 31) * 4;
            *(float4*)&g_logits[((size_t)bh * TT + qt0 + r) * KVL + kv0 + c] = neg;
        }
        return;
    }

    int wy = wid >> 2, wx = wid & 3;

    wmma::fragment<wmma::accumulator, 16, 16, 16, float> acc[4][2];
#pragma unroll
    for (int mi = 0; mi < 4; mi++)
#pragma unroll
        for (int ni = 0; ni < 2; ni++) wmma::fill_fragment(acc[mi][ni], 0.f);

    const __nv_bfloat16* Ah = g_Acat_h + ((size_t)bh * TT + qt0) * 1088;
    const __nv_bfloat16* Al = g_Acat_l + ((size_t)bh * TT + qt0) * 1088;

    for (int kc = 0; kc < 34; kc++) {
        const __nv_bfloat16 *Bhp, *Blp;
        int bld, bcol;
        if (kc < 2) {
            Bhp = g_Bkey_h + (size_t)bh * KVL * 64;
            Blp = g_Bkey_l + (size_t)bh * KVL * 64;
            bld = 64; bcol = kc * 32;
        } else {
            Bhp = g_Ktrig_h; Blp = g_Ktrig_l;
            bld = 1024; bcol = (kc - 2) * 32;
        }
        __syncthreads();
#pragma unroll
        for (int t = tid; t < 512; t += 256) {
            int row = t >> 2, seg = (t & 3) * 8;
            *(uint4*)&sAh[row * PADA + seg] = *(const uint4*)(Ah + (size_t)row * 1088 + kc * 32 + seg);
            *(uint4*)&sAl[row * PADA + seg] = *(const uint4*)(Al + (size_t)row * 1088 + kc * 32 + seg);
            *(uint4*)&sBh[row * PADA + seg] = *(const uint4*)(Bhp + (size_t)(kv0 + row) * bld + bcol + seg);
            *(uint4*)&sBl[row * PADA + seg] = *(const uint4*)(Blp + (size_t)(kv0 + row) * bld + bcol + seg);
        }
        __syncthreads();
#pragma unroll
        for (int ks = 0; ks < 2; ks++) {
            wmma::fragment<wmma::matrix_a, 16, 16, 16, __nv_bfloat16, wmma::row_major> fah[4], fal[4];
            wmma::fragment<wmma::matrix_b, 16, 16, 16, __nv_bfloat16, wmma::col_major> fbh[2], fbl[2];
#pragma unroll
            for (int mi = 0; mi < 4; mi++) {
                wmma::load_matrix_sync(fah[mi], &sAh[(wy * 64 + mi * 16) * PADA + ks * 16], PADA);
                wmma::load_matrix_sync(fal[mi], &sAl[(wy * 64 + mi * 16) * PADA + ks * 16], PADA);
            }
#pragma unroll
            for (int ni = 0; ni < 2; ni++) {
                wmma::load_matrix_sync(fbh[ni], &sBh[(wx * 32 + ni * 16) * PADA + ks * 16], PADA);
                wmma::load_matrix_sync(fbl[ni], &sBl[(wx * 32 + ni * 16) * PADA + ks * 16], PADA);
            }
#pragma unroll
            for (int mi = 0; mi < 4; mi++)
#pragma unroll
                for (int ni = 0; ni < 2; ni++) {
                    wmma::mma_sync(acc[mi][ni], fah[mi], fbh[ni], acc[mi][ni]);
                    wmma::mma_sync(acc[mi][ni], fah[mi], fbl[ni], acc[mi][ni]);
                    wmma::mma_sync(acc[mi][ni], fal[mi], fbh[ni], acc[mi][ni]);
                }
        }
    }

    __syncthreads();
    float* sOut = (float*)sAh + wid * 16 * OUTLD;
    const float* ub = g_ubias + (size_t)bh * KVL;
#pragma unroll
    for (int mi = 0; mi < 4; mi++)
#pragma unroll
        for (int ni = 0; ni < 2; ni++) {
            wmma::store_matrix_sync(sOut, acc[mi][ni], OUTLD, wmma::mem_row_major);
            __syncwarp();
#pragma unroll
            for (int e = 0; e < 8; e++) {
                int idx = lane * 8 + e;
                int r = idx >> 4, c = idx & 15;
                int qt = qt0 + wy * 64 + mi * 16 + r;
                int kv = kv0 + wx * 32 + ni * 16 + c;
                float x = (sOut[r * OUTLD + c] + ub[kv]) * 0.125f;
                if (kv - qt >= 513) x -= LARGE_BIAS;
                int cm = (kv < MMs) ? smask[b * MMs + kv] : qmask[b * TT + (kv - MMs)];
                if (!cm) x -= LARGE_BIAS;
                g_logits[((size_t)bh * TT + qt) * KVL + kv] = x;
            }
            __syncwarp();
        }
}

// ---------------- softmax -> bf16 hi/lo weights ----------------
__global__ void __launch_bounds__(256) k_softmax() {
    size_t ro = (size_t)blockIdx.x * KVL;
    float* row = g_logits + ro;
    int tid = threadIdx.x, lane = tid & 31, wid = tid >> 5;
    __shared__ float red[8];
    __shared__ float bc;
    float v[4], mx = -1e30f;
#pragma unroll
    for (int i = 0; i < 4; i++) { v[i] = row[tid + i * 256]; mx = fmaxf(mx, v[i]); }
#pragma unroll
    for (int o = 16; o > 0; o >>= 1) mx = fmaxf(mx, __shfl_xor_sync(~0u, mx, o));
    if (!lane) red[wid] = mx;
    __syncthreads();
    if (!wid) {
        float m2 = (lane < 8) ? red[lane] : -1e30f;
#pragma unroll
        for (int o = 16; o > 0; o >>= 1) m2 = fmaxf(m2, __shfl_xor_sync(~0u, m2, o));
        if (!lane) bc = m2;
    }
    __syncthreads();
    mx = bc;
    float s = 0.f;
#pragma unroll
    for (int i = 0; i < 4; i++) { v[i] = expf(v[i] - mx); s += v[i]; }
#pragma unroll
    for (int o = 16; o > 0; o >>= 1) s += __shfl_xor_sync(~0u, s, o);
    __syncthreads();
    if (!lane) red[wid] = s;
    __syncthreads();
    if (!wid) {
        float s2 = (lane < 8) ? red[lane] : 0.f;
#pragma unroll
        for (int o = 16; o > 0; o >>= 1) s2 += __shfl_xor_sync(~0u, s2, o);
        if (!lane) bc = s2;
    }
    __syncthreads();
    float inv = 1.f / bc;
#pragma unroll
    for (int i = 0; i < 4; i++) {
        float w = v[i] * inv;
        __nv_bfloat16 hi, lo;
        bsplit(w, hi, lo);
        g_Wh[ro + tid + i * 256] = hi;
        g_Wl[ro + tid + i * 256] = lo;
    }
}

// ---------------- host ----------------
static float* symaddr(const void* s) { void* p = 0; cudaGetSymbolAddress(&p, s); return (float*)p; }
static __nv_bfloat16* symaddrb(const void* s) { void* p = 0; cudaGetSymbolAddress(&p, s); return (__nv_bfloat16*)p; }

extern "C" void kernel_launch(void* const* d_in, const int* in_sizes, int n_in,
                              void* d_out, int out_size) {
    (void)in_sizes; (void)n_in; (void)out_size;
    const float* inputs = (const float*)d_in[0];
    const float* state  = (const float*)d_in[1];
    const int* mask     = (const int*)d_in[2];
    const int* smask    = (const int*)d_in[3];
    const float* qW = (const float*)d_in[4];
    const float* kW = (const float*)d_in[5];
    const float* rW = (const float*)d_in[6];
    const float* vW = (const float*)d_in[7];
    const float* uW = (const float*)d_in[8];
    const float* vv = (const float*)d_in[9];
    const float* oW = (const float*)d_in[10];
    float* out = (float*)d_out;

    float* pQuery = symaddr(g_query);
    float* pKey   = symaddr(g_key);
    float* pValue = symaddr(g_value);
    float* pVrel  = symaddr(g_vrel);
    float* pQv    = symaddr(g_qv);
    float* pAtt   = symaddr(g_att);

    __nv_bfloat16 *inh = symaddrb(g_inh), *inl = symaddrb(g_inl);
    __nv_bfloat16 *conh = symaddrb(g_conh), *conl = symaddrb(g_conl);
    __nv_bfloat16 *qWh = symaddrb(g_qWh), *qWl = symaddrb(g_qWl);
    __nv_bfloat16 *kWh = symaddrb(g_kWh), *kWl = symaddrb(g_kWl);
    __nv_bfloat16 *vWh = symaddrb(g_vWh), *vWl = symaddrb(g_vWl);
    __nv_bfloat16 *oWh = symaddrb(g_oWh), *oWl = symaddrb(g_oWl);
    __nv_bfloat16 *relh = symaddrb(g_relh), *rell = symaddrb(g_rell);
    __nv_bfloat16 *qh = symaddrb(g_qh), *ql = symaddrb(g_ql);
    __nv_bfloat16 *valh = symaddrb(g_valh), *vall = symaddrb(g_vall);
    __nv_bfloat16 *atth = symaddrb(g_atth), *attl = symaddrb(g_attl);
    __nv_bfloat16 *Wh = symaddrb(g_Wh), *Wl = symaddrb(g_Wl);

    const int* nomask = (const int*)0;
    const float* nobias = (const float*)0;

    // elementwise prep
    k_concat<<<(BB * KVL * DDim + 255) / 256, 256>>>(inputs, state);
    k_relT<<<(DDim * 512 + 255) / 256, 256>>>(rW);
    k_vrel<<<(HH * DDim * 32 + 255) / 256, 256>>>(vv, rW);
    k_qtrig<<<(TT * DDim + 255) / 256, 256>>>();
    k_ktrig<<<(KVL * DDim + 255) / 256, 256>>>();
    k_split<<<(BB * TT * DDim + 255) / 256, 256>>>(inputs, inh, inl, BB * TT * DDim);
    k_split<<<(512 * 512 + 255) / 256, 256>>>(qW, qWh, qWl, 512 * 512);
    k_split<<<(512 * 512 + 255) / 256, 256>>>(kW, kWh, kWl, 512 * 512);
    k_split<<<(512 * 512 + 255) / 256, 256>>>(vW, vWh, vWl, 512 * 512);
    k_split<<<(512 * 512 + 255) / 256, 256>>>(oW, oWh, oWl, 512 * 512);

    // query = inputs @ qW (rowmask)   M=1024 N=512 K=512
    gemmw<<<dim3(8, 8, 1), 256>>>(inh, inl, qWh, qWl, pQuery,
        512, 512, 512, 512, 0, 0, 0, 0, 0, 0, 1, mask, nobias, 0, 0);
    // key / value = concat @ W        M=2048 N=512 K=512
    gemmw<<<dim3(8, 16, 1), 256>>>(conh, conl, kWh, kWl, pKey,
        512, 512, 512, 512, 0, 0, 0, 0, 0, 0, 1, nomask, nobias, 0, 0);
    gemmw<<<dim3(8, 16, 1), 256>>>(conh, conl, vWh, vWl, pValue,
        512, 512, 512, 512, 0, 0, 0, 0, 0, 0, 1, nomask, nobias, 0, 0);

    k_split<<<(BB * TT * 512 + 255) / 256, 256>>>(pQuery, qh, ql, BB * TT * 512);
    k_split<<<(BB * KVL * 512 + 255) / 256, 256>>>(pValue, valh, vall, BB * KVL * 512);

    // qv per-head: M=1024 N=512 K=64, + vrel bias
    gemmw<<<dim3(8, 8, HH), 256>>>(qh, ql, relh, rell, pQv,
        512, 512, 4096, 64,
        0, 64, 0, (long)UU * DDim, 0, 512, HH, nomask, pVrel, 512, 0);

    k_ubias<<<(BB * HH * KVL + 255) / 256, 256>>>(uW);
    k_bkey<<<(16 * KVL * UU + 255) / 256, 256>>>();
    k_acat_c<<<(16 * TT * UU + 255) / 256, 256>>>();
    k_acat_p<<<(16 * TT * DDim + 255) / 256, 256>>>();

    // logits on tensor cores
    k_logits_wmma<<<dim3(KVL / 128, TT / 128, 16), 256>>>(mask, smask);

    k_softmax<<<BB * HH * TT, 256>>>();

    // attended = weights @ value   per (b,h): M=512 N=64 K=1024, causal K-truncation
    gemmw<<<dim3(1, 4, 16), 256>>>(Wh, Wl, valh, vall, pAtt,
        KVL, 512, 512, KVL,
        (long)HH * TT * KVL, (long)TT * KVL,
        (long)KVL * 512, 64,
        (long)TT * 512, 64, HH, nomask, nobias, 0, 1);

    k_split<<<(BB * TT * 512 + 255) / 256, 256>>>(pAtt, atth, attl, BB * TT * 512);

    // out = attended @ output_W    M=1024 N=512 K=512
    gemmw<<<dim3(8, 8, 1), 256>>>(atth, attl, oWh, oWl, out,
        512, 512, 512, 512, 0, 0, 0, 0, 0, 0, 1, nomask, nobias, 0, 0);
}

// round 8
// speedup vs baseline: 1.3830x; 1.0598x over previous
#include <cuda_runtime.h>
#include <cuda_bf16.h>
#include <mma.h>
#include <math.h>

using namespace nvcuda;

#define BB 2
#define TT 512
#define MMs 512
#define DDim 512
#define HH 8
#define UU 64
#define KVL 1024
#define LARGE_BIAS 10000.0f

// ---------------- scratch (static device globals; no allocation) ----------------
__device__ __align__(128) float g_query[BB * TT * HH * UU];
__device__ __align__(128) float g_key[BB * KVL * HH * UU];
__device__ __align__(128) float g_value[BB * KVL * HH * UU];
__device__ __align__(128) float g_vrel[HH * DDim];
__device__ __align__(128) float g_qv[BB * TT * HH * DDim];
__device__ __align__(128) float g_ubias[BB * HH * KVL];
__device__ __align__(128) float g_logits[BB * HH * TT * KVL];
__device__ __align__(128) float g_att[BB * TT * HH * UU];
__device__ __align__(128) float2 g_qtrig[TT * DDim];
// bf16 hi/lo operand pools
__device__ __align__(128) __nv_bfloat16 g_inh[TT * BB * DDim],  g_inl[TT * BB * DDim];
__device__ __align__(128) __nv_bfloat16 g_conh[BB * KVL * DDim], g_conl[BB * KVL * DDim];
__device__ __align__(128) __nv_bfloat16 g_qWh[DDim * 512], g_qWl[DDim * 512];
__device__ __align__(128) __nv_bfloat16 g_kWh[DDim * 512], g_kWl[DDim * 512];
__device__ __align__(128) __nv_bfloat16 g_vWh[DDim * 512], g_vWl[DDim * 512];
__device__ __align__(128) __nv_bfloat16 g_oWh[HH * UU * 512], g_oWl[HH * UU * 512];
__device__ __align__(128) __nv_bfloat16 g_relh[HH * UU * DDim], g_rell[HH * UU * DDim];
__device__ __align__(128) __nv_bfloat16 g_qh[BB * TT * 512], g_ql[BB * TT * 512];
__device__ __align__(128) __nv_bfloat16 g_valh[BB * KVL * 512], g_vall[BB * KVL * 512];
__device__ __align__(128) __nv_bfloat16 g_atth[BB * TT * 512], g_attl[BB * TT * 512];
__device__ __align__(128) __nv_bfloat16 g_Wh[16 * TT * KVL], g_Wl[16 * TT * KVL];
// logits tensor-path operands
__device__ __align__(128) __nv_bfloat16 g_Ktrig_h[KVL * 1024], g_Ktrig_l[KVL * 1024];
__device__ __align__(128) __nv_bfloat16 g_Bkey_h[16 * KVL * UU], g_Bkey_l[16 * KVL * UU];
__device__ __align__(128) __nv_bfloat16 g_Acat_h[16 * TT * 1088], g_Acat_l[16 * TT * 1088];

__device__ __forceinline__ void bsplit(float x, __nv_bfloat16& h, __nv_bfloat16& l) {
    h = __float2bfloat16(x);
    l = __float2bfloat16(x - __bfloat162float(h));
}
__device__ __forceinline__ void cpa16(void* sdst, const void* gsrc) {
    unsigned s = (unsigned)__cvta_generic_to_shared(sdst);
    asm volatile("cp.async.cg.shared.global [%0], [%1], 16;" :: "r"(s), "l"(gsrc));
}
#define CP_COMMIT() asm volatile("cp.async.commit_group;" ::: "memory")
#define CP_WAIT1()  asm volatile("cp.async.wait_group 1;" ::: "memory")
#define CP_WAIT0()  asm volatile("cp.async.wait_group 0;" ::: "memory")

// ---------------- elementwise prep ----------------
__global__ void k_split(const float* __restrict__ s, __nv_bfloat16* __restrict__ h,
                        __nv_bfloat16* __restrict__ l, int n) {
    int i = blockIdx.x * blockDim.x + threadIdx.x;
    if (i >= n) return;
    __nv_bfloat16 hi, lo;
    bsplit(s[i], hi, lo);
    h[i] = hi; l[i] = lo;
}
__global__ void k_splitw(const float* __restrict__ s0, const float* __restrict__ s1,
                         const float* __restrict__ s2, const float* __restrict__ s3) {
    int i = blockIdx.x * blockDim.x + threadIdx.x;
    if (i >= 4 * 262144) return;
    int w = i >> 18, j = i & 262143;
    const float* s = (w == 0) ? s0 : (w == 1) ? s1 : (w == 2) ? s2 : s3;
    __nv_bfloat16 hi, lo;
    bsplit(s[j], hi, lo);
    if (w == 0) { g_qWh[j] = hi; g_qWl[j] = lo; }
    else if (w == 1) { g_kWh[j] = hi; g_kWl[j] = lo; }
    else if (w == 2) { g_vWh[j] = hi; g_vWl[j] = lo; }
    else { g_oWh[j] = hi; g_oWl[j] = lo; }
}
__global__ void k_concat(const float* __restrict__ in, const float* __restrict__ st) {
    int i = blockIdx.x * blockDim.x + threadIdx.x;
    if (i >= BB * KVL * DDim) return;
    int d = i & 511, j = (i >> 9) & 1023, b = i >> 19;
    float v = (j < MMs) ? st[((size_t)(b * MMs + j)) * 512 + d]
                        : in[((size_t)(b * TT + (j - MMs))) * 512 + d];
    __nv_bfloat16 hi, lo;
    bsplit(v, hi, lo);
    g_conh[i] = hi; g_conl[i] = lo;
}
__global__ void k_relT(const float* __restrict__ rW) {
    int i = blockIdx.x * blockDim.x + threadIdx.x;
    if (i >= DDim * 512) return;
    __nv_bfloat16 hi, lo;
    bsplit(rW[i], hi, lo);
    size_t o = (size_t)(i & 511) * 512 + (i >> 9);
    g_relh[o] = hi; g_rell[o] = lo;
}
__global__ void k_vrel(const float* __restrict__ vv, const float* __restrict__ rW) {
    int g = (blockIdx.x * blockDim.x + threadIdx.x) >> 5, lane = threadIdx.x & 31;
    if (g >= HH * DDim) return;
    int h = g >> 9, d = g & 511;
    const float* rp = rW + (size_t)d * 512 + h * 64;
    const float* vp = vv + h * 64;
    float s = rp[lane] * vp[lane] + rp[lane + 32] * vp[lane + 32];
#pragma unroll
    for (int o = 16; o > 0; o >>= 1) s += __shfl_xor_sync(~0u, s, o);
    if (!lane) g_vrel[h * 512 + d] = s;
}
__global__ void k_ubias(const float* __restrict__ uW) {
    int i = blockIdx.x * blockDim.x + threadIdx.x;
    if (i >= BB * HH * KVL) return;
    int kv = i & 1023, h = (i >> 10) & 7, b = i >> 13;
    const float* kp = g_key + ((size_t)(b * KVL + kv)) * 512 + h * 64;
    const float* up = uW + h * 64;
    float s = 0.f;
#pragma unroll
    for (int u = 0; u < 64; u++) s = fmaf(kp[u], up[u], s);
    g_ubias[i] = s;
}
__global__ void k_qtrig() {
    int i = blockIdx.x * blockDim.x + threadIdx.x;
    if (i >= TT * DDim) return;
    int d = i & 511, qt = i >> 9;
    float invw = powf(10000.0f, -2.0f * (float)d / 512.0f);
    float off = (d & 1) ? 1.57079632679489662f : 0.0f;
    float s, c;
    sincosf((float)(qt + 512) * invw + off, &s, &c);
    g_qtrig[i] = make_float2(s, c);
}
__global__ void k_ktrig() {
    int i = blockIdx.x * blockDim.x + threadIdx.x;
    if (i >= KVL * DDim) return;
    int d = i & 511, kv = i >> 9;
    float invw = powf(10000.0f, -2.0f * (float)d / 512.0f);
    float s, c;
    sincosf((float)kv * invw, &s, &c);
    __nv_bfloat16 ch, cl, sh, sl;
    bsplit(c, ch, cl);
    bsplit(s, sh, sl);
    __nv_bfloat162 vh, vl;
    vh.x = ch; vh.y = sh; vl.x = cl; vl.y = sl;
    *(__nv_bfloat162*)&g_Ktrig_h[(size_t)kv * 1024 + 2 * d] = vh;
    *(__nv_bfloat162*)&g_Ktrig_l[(size_t)kv * 1024 + 2 * d] = vl;
}
__global__ void k_bkey() {
    int i = blockIdx.x * blockDim.x + threadIdx.x;
    if (i >= 16 * KVL * UU) return;
    int u = i & 63, kv = (i >> 6) & 1023, bh = i >> 16;
    int b = bh >> 3, h = bh & 7;
    __nv_bfloat16 hi, lo;
    bsplit(g_key[(size_t)(b * KVL + kv) * 512 + h * 64 + u], hi, lo);
    g_Bkey_h[i] = hi; g_Bkey_l[i] = lo;
}
__global__ void k_acat_c() {
    int i = blockIdx.x * blockDim.x + threadIdx.x;
    if (i >= 16 * TT * UU) return;
    int u = i & 63, qt = (i >> 6) & 511, bh = i >> 15;
    int b = bh >> 3, h = bh & 7;
    __nv_bfloat16 hi, lo;
    bsplit(g_query[(size_t)(b * TT + qt) * 512 + h * 64 + u], hi, lo);
    size_t o = ((size_t)bh * TT + qt) * 1088 + u;
    g_Acat_h[o] = hi; g_Acat_l[o] = lo;
}
__global__ void k_acat_p() {
    int i = blockIdx.x * blockDim.x + threadIdx.x;
    if (i >= 16 * TT * DDim) return;
    int d = i & 511, qt = (i >> 9) & 511, bh = i >> 18;
    int b = bh >> 3, h = bh & 7;
    float q = g_qv[(size_t)(b * TT + qt) * 4096 + h * 512 + d];
    float2 tr = g_qtrig[qt * 512 + d];
    __nv_bfloat16 sh, sl, ch, cl;
    bsplit(q * tr.x, sh, sl);
    bsplit(-q * tr.y, ch, cl);
    size_t o = ((size_t)bh * TT + qt) * 1088 + 64 + 2 * d;
    __nv_bfloat162 vh, vl;
    vh.x = sh; vh.y = ch; vl.x = sl; vl.y = cl;
    *(__nv_bfloat162*)&g_Acat_h[o] = vh;
    *(__nv_bfloat162*)&g_Acat_l[o] = vl;
}

// ---------------- generic WMMA hi/lo GEMM (known-good, single-buffered) ----------------
#define PADA 40
#define PADB 72
#define OUTLD 20

__global__ void __launch_bounds__(256) gemmw(
    const __nv_bfloat16* __restrict__ Ah, const __nv_bfloat16* __restrict__ Al,
    const __nv_bfloat16* __restrict__ Bh, const __nv_bfloat16* __restrict__ Bl,
    float* __restrict__ C,
    int lda, int ldb, int ldc, int Kdim,
    long az1, long az2, long bz1, long bz2, long cz1, long cz2, int Z2,
    const int* __restrict__ rowmask, const float* __restrict__ bias, long biasz2,
    int causal)
{
    __shared__ __nv_bfloat16 sAh[128 * PADA];
    __shared__ __nv_bfloat16 sAl[128 * PADA];
    __shared__ __nv_bfloat16 sBh[32 * PADB];
    __shared__ __nv_bfloat16 sBl[32 * PADB];

    int z = blockIdx.z, z1 = z / Z2, z2 = z - z1 * Z2;
    const __nv_bfloat16* Ahp = Ah + (size_t)z1 * az1 + (size_t)z2 * az2;
    const __nv_bfloat16* Alp = Al + (size_t)z1 * az1 + (size_t)z2 * az2;
    const __nv_bfloat16* Bhp = Bh + (size_t)z1 * bz1 + (size_t)z2 * bz2;
    const __nv_bfloat16* Blp = Bl + (size_t)z1 * bz1 + (size_t)z2 * bz2;
    float* Cp = C + (size_t)z1 * cz1 + (size_t)z2 * cz2;
    const float* biasp = bias ? (bias + (size_t)z2 * biasz2) : (const float*)0;

    int m0 = blockIdx.y * 128, n0 = blockIdx.x * 64;
    int tid = threadIdx.x, wid = tid >> 5, lane = tid & 31;
    int wy = wid >> 1, wx = wid & 1;

    wmma::fragment<wmma::accumulator, 16, 16, 16, float> acc[2][2];
#pragma unroll
    for (int mi = 0; mi < 2; mi++)
#pragma unroll
        for (int ni = 0; ni < 2; ni++) wmma::fill_fragment(acc[mi][ni], 0.f);

    int Klim = Kdim;
    if (causal) {
        int km = m0 + 640;
        Klim = (km < Kdim) ? ((km + 31) & ~31) : Kdim;
    }

    int arow = tid >> 1, asg = (tid & 1) * 16;
    int brow = tid >> 3, bsg = (tid & 7) * 8;

    for (int kc = 0; kc < Klim; kc += 32) {
        __syncthreads();
        *(uint4*)&sAh[arow * PADA + asg]     = *(const uint4*)(Ahp + (size_t)(m0 + arow) * lda + kc + asg);
        *(uint4*)&sAh[arow * PADA + asg + 8] = *(const uint4*)(Ahp + (size_t)(m0 + arow) * lda + kc + asg + 8);
        *(uint4*)&sAl[arow * PADA + asg]     = *(const uint4*)(Alp + (size_t)(m0 + arow) * lda + kc + asg);
        *(uint4*)&sAl[arow * PADA + asg + 8] = *(const uint4*)(Alp + (size_t)(m0 + arow) * lda + kc + asg + 8);
        *(uint4*)&sBh[brow * PADB + bsg]     = *(const uint4*)(Bhp + (size_t)(kc + brow) * ldb + n0 + bsg);
        *(uint4*)&sBl[brow * PADB + bsg]     = *(const uint4*)(Blp + (size_t)(kc + brow) * ldb + n0 + bsg);
        __syncthreads();
#pragma unroll
        for (int ks = 0; ks < 2; ks++) {
            wmma::fragment<wmma::matrix_a, 16, 16, 16, __nv_bfloat16, wmma::row_major> fah[2], fal[2];
            wmma::fragment<wmma::matrix_b, 16, 16, 16, __nv_bfloat16, wmma::row_major> fbh[2], fbl[2];
#pragma unroll
            for (int mi = 0; mi < 2; mi++) {
                wmma::load_matrix_sync(fah[mi], &sAh[(wy * 32 + mi * 16) * PADA + ks * 16], PADA);
                wmma::load_matrix_sync(fal[mi], &sAl[(wy * 32 + mi * 16) * PADA + ks * 16], PADA);
            }
#pragma unroll
            for (int ni = 0; ni < 2; ni++) {
                wmma::load_matrix_sync(fbh[ni], &sBh[ks * 16 * PADB + wx * 32 + ni * 16], PADB);
                wmma::load_matrix_sync(fbl[ni], &sBl[ks * 16 * PADB + wx * 32 + ni * 16], PADB);
            }
#pragma unroll
            for (int mi = 0; mi < 2; mi++)
#pragma unroll
                for (int ni = 0; ni < 2; ni++) {
                    wmma::mma_sync(acc[mi][ni], fah[mi], fbh[ni], acc[mi][ni]);
                    wmma::mma_sync(acc[mi][ni], fah[mi], fbl[ni], acc[mi][ni]);
                    wmma::mma_sync(acc[mi][ni], fal[mi], fbh[ni], acc[mi][ni]);
                }
        }
    }

    __syncthreads();
    float* sOut = (float*)sAh + wid * 16 * OUTLD;
#pragma unroll
    for (int mi = 0; mi < 2; mi++)
#pragma unroll
        for (int ni = 0; ni < 2; ni++) {
            wmma::store_matrix_sync(sOut, acc[mi][ni], OUTLD, wmma::mem_row_major);
            __syncwarp();
#pragma unroll
            for (int e = 0; e < 8; e++) {
                int idx = lane * 8 + e;
                int r = idx >> 4, c = idx & 15;
                int mg = m0 + wy * 32 + mi * 16 + r;
                int ng = n0 + wx * 32 + ni * 16 + c;
                float x = sOut[r * OUTLD + c];
                if (biasp) x += biasp[ng];
                if (rowmask) x *= rowmask[mg] ? 1.f : 0.f;
                Cp[(size_t)mg * ldc + ng] = x;
            }
            __syncwarp();
        }
}

// ---------------- WMMA logits, cp.async 2-stage pipelined ----------------
#define LTILE 10240                       // 128 * PADA * 2 bytes
#define LSTG  (4 * LTILE)                 // Ah | Al | Bh | Bl per stage

__global__ void __launch_bounds__(256, 1) k_logits_wmma(
    const int* __restrict__ qmask, const int* __restrict__ smask)
{
    extern __shared__ char dsm[];
    int tid = threadIdx.x, wid = tid >> 5, lane = tid & 31;
    int kv0 = blockIdx.x * 128, qt0 = blockIdx.y * 128, bh = blockIdx.z;
    int b = bh >> 3;

    if (kv0 >= qt0 + 640) {   // fully causal-masked tile
        float4 neg = make_float4(-LARGE_BIAS, -LARGE_BIAS, -LARGE_BIAS, -LARGE_BIAS);
        for (int t = tid; t < 128 * 32; t += 256) {
            int r = t >> 5, c = (t & 31) * 4;
            *(float4*)&g_logits[((size_t)bh * TT + qt0 + r) * KVL + kv0 + c] = neg;
        }
        return;
    }

    int wy = wid >> 2, wx = wid & 3;      // warp tile 64 rows x 32 cols

    wmma::fragment<wmma::accumulator, 16, 16, 16, float> acc[4][2];
#pragma unroll
    for (int mi = 0; mi < 4; mi++)
#pragma unroll
        for (int ni = 0; ni < 2; ni++) wmma::fill_fragment(acc[mi][ni], 0.f);

    const __nv_bfloat16* Ah = g_Acat_h + ((size_t)bh * TT + qt0) * 1088;
    const __nv_bfloat16* Al = g_Acat_l + ((size_t)bh * TT + qt0) * 1088;
    const __nv_bfloat16* BKh = g_Bkey_h + (size_t)bh * KVL * 64;
    const __nv_bfloat16* BKl = g_Bkey_l + (size_t)bh * KVL * 64;

    auto issue = [&](int kc, int s) {
        const __nv_bfloat16 *Bhp, *Blp;
        size_t bld;
        int bcol;
        if (kc < 2) { Bhp = BKh; Blp = BKl; bld = 64; bcol = kc * 32; }
        else        { Bhp = g_Ktrig_h; Blp = g_Ktrig_l; bld = 1024; bcol = (kc - 2) * 32; }
        char* base = dsm + s * LSTG;
#pragma unroll
        for (int t = tid; t < 512; t += 256) {
            int row = t >> 2, seg = (t & 3) * 8;
            size_t so = ((size_t)row * PADA + seg) * 2;
            cpa16(base + so,             Ah + (size_t)row * 1088 + kc * 32 + seg);
            cpa16(base + LTILE + so,     Al + (size_t)row * 1088 + kc * 32 + seg);
            cpa16(base + 2 * LTILE + so, Bhp + (size_t)(kv0 + row) * bld + bcol + seg);
            cpa16(base + 3 * LTILE + so, Blp + (size_t)(kv0 + row) * bld + bcol + seg);
        }
        CP_COMMIT();
    };

    issue(0, 0);
    for (int kc = 0; kc < 34; kc++) {
        if (kc + 1 < 34) { issue(kc + 1, (kc + 1) & 1); CP_WAIT1(); }
        else             { CP_WAIT0(); }
        __syncthreads();
        char* base = dsm + (kc & 1) * LSTG;
        __nv_bfloat16* sAh = (__nv_bfloat16*)base;
        __nv_bfloat16* sAl = (__nv_bfloat16*)(base + LTILE);
        __nv_bfloat16* sBh = (__nv_bfloat16*)(base + 2 * LTILE);
        __nv_bfloat16* sBl = (__nv_bfloat16*)(base + 3 * LTILE);
#pragma unroll
        for (int ks = 0; ks < 2; ks++) {
            wmma::fragment<wmma::matrix_b, 16, 16, 16, __nv_bfloat16, wmma::col_major> fbh[2], fbl[2];
#pragma unroll
            for (int ni = 0; ni < 2; ni++) {
                wmma::load_matrix_sync(fbh[ni], &sBh[(wx * 32 + ni * 16) * PADA + ks * 16], PADA);
                wmma::load_matrix_sync(fbl[ni], &sBl[(wx * 32 + ni * 16) * PADA + ks * 16], PADA);
            }
#pragma unroll
            for (int mi = 0; mi < 4; mi++) {
                wmma::fragment<wmma::matrix_a, 16, 16, 16, __nv_bfloat16, wmma::row_major> fah, fal;
                wmma::load_matrix_sync(fah, &sAh[(wy * 64 + mi * 16) * PADA + ks * 16], PADA);
                wmma::load_matrix_sync(fal, &sAl[(wy * 64 + mi * 16) * PADA + ks * 16], PADA);
#pragma unroll
                for (int ni = 0; ni < 2; ni++) {
                    wmma::mma_sync(acc[mi][ni], fah, fbh[ni], acc[mi][ni]);
                    wmma::mma_sync(acc[mi][ni], fah, fbl[ni], acc[mi][ni]);
                    wmma::mma_sync(acc[mi][ni], fal, fbh[ni], acc[mi][ni]);
                }
            }
        }
        __syncthreads();
    }

    float* sOut = (float*)dsm + wid * 16 * OUTLD;
    const float* ub = g_ubias + (size_t)bh * KVL;
#pragma unroll
    for (int mi = 0; mi < 4; mi++)
#pragma unroll
        for (int ni = 0; ni < 2; ni++) {
            wmma::store_matrix_sync(sOut, acc[mi][ni], OUTLD, wmma::mem_row_major);
            __syncwarp();
#pragma unroll
            for (int e = 0; e < 8; e++) {
                int idx = lane * 8 + e;
                int r = idx >> 4, c = idx & 15;
                int qt = qt0 + wy * 64 + mi * 16 + r;
                int kv = kv0 + wx * 32 + ni * 16 + c;
                float x = (sOut[r * OUTLD + c] + ub[kv]) * 0.125f;
                if (kv - qt >= 513) x -= LARGE_BIAS;
                int cm = (kv < MMs) ? smask[b * MMs + kv] : qmask[b * TT + (kv - MMs)];
                if (!cm) x -= LARGE_BIAS;
                g_logits[((size_t)bh * TT + qt) * KVL + kv] = x;
            }
            __syncwarp();
        }
}

// ---------------- softmax -> bf16 hi/lo weights ----------------
__global__ void __launch_bounds__(256) k_softmax() {
    size_t ro = (size_t)blockIdx.x * KVL;
    float* row = g_logits + ro;
    int tid = threadIdx.x, lane = tid & 31, wid = tid >> 5;
    __shared__ float red[8];
    __shared__ float bc;
    float v[4], mx = -1e30f;
#pragma unroll
    for (int i = 0; i < 4; i++) { v[i] = row[tid + i * 256]; mx = fmaxf(mx, v[i]); }
#pragma unroll
    for (int o = 16; o > 0; o >>= 1) mx = fmaxf(mx, __shfl_xor_sync(~0u, mx, o));
    if (!lane) red[wid] = mx;
    __syncthreads();
    if (!wid) {
        float m2 = (lane < 8) ? red[lane] : -1e30f;
#pragma unroll
        for (int o = 16; o > 0; o >>= 1) m2 = fmaxf(m2, __shfl_xor_sync(~0u, m2, o));
        if (!lane) bc = m2;
    }
    __syncthreads();
    mx = bc;
    float s = 0.f;
#pragma unroll
    for (int i = 0; i < 4; i++) { v[i] = expf(v[i] - mx); s += v[i]; }
#pragma unroll
    for (int o = 16; o > 0; o >>= 1) s += __shfl_xor_sync(~0u, s, o);
    __syncthreads();
    if (!lane) red[wid] = s;
    __syncthreads();
    if (!wid) {
        float s2 = (lane < 8) ? red[lane] : 0.f;
#pragma unroll
        for (int o = 16; o > 0; o >>= 1) s2 += __shfl_xor_sync(~0u, s2, o);
        if (!lane) bc = s2;
    }
    __syncthreads();
    float inv = 1.f / bc;
#pragma unroll
    for (int i = 0; i < 4; i++) {
        float w = v[i] * inv;
        __nv_bfloat16 hi, lo;
        bsplit(w, hi, lo);
        g_Wh[ro + tid + i * 256] = hi;
        g_Wl[ro + tid + i * 256] = lo;
    }
}

// ---------------- host ----------------
static float* symaddr(const void* s) { void* p = 0; cudaGetSymbolAddress(&p, s); return (float*)p; }
static __nv_bfloat16* symaddrb(const void* s) { void* p = 0; cudaGetSymbolAddress(&p, s); return (__nv_bfloat16*)p; }

extern "C" void kernel_launch(void* const* d_in, const int* in_sizes, int n_in,
                              void* d_out, int out_size) {
    (void)in_sizes; (void)n_in; (void)out_size;
    const float* inputs = (const float*)d_in[0];
    const float* state  = (const float*)d_in[1];
    const int* mask     = (const int*)d_in[2];
    const int* smask    = (const int*)d_in[3];
    const float* qW = (const float*)d_in[4];
    const float* kW = (const float*)d_in[5];
    const float* rW = (const float*)d_in[6];
    const float* vW = (const float*)d_in[7];
    const float* uW = (const float*)d_in[8];
    const float* vv = (const float*)d_in[9];
    const float* oW = (const float*)d_in[10];
    float* out = (float*)d_out;

    float* pQuery = symaddr(g_query);
    float* pValue = symaddr(g_value);
    float* pVrel  = symaddr(g_vrel);
    float* pQv    = symaddr(g_qv);
    float* pAtt   = symaddr(g_att);

    __nv_bfloat16 *inh = symaddrb(g_inh), *inl = symaddrb(g_inl);
    __nv_bfloat16 *conh = symaddrb(g_conh), *conl = symaddrb(g_conl);
    __nv_bfloat16 *qWh = symaddrb(g_qWh), *qWl = symaddrb(g_qWl);
    __nv_bfloat16 *kWh = symaddrb(g_kWh), *kWl = symaddrb(g_kWl);
    __nv_bfloat16 *vWh = symaddrb(g_vWh), *vWl = symaddrb(g_vWl);
    __nv_bfloat16 *oWh = symaddrb(g_oWh), *oWl = symaddrb(g_oWl);
    __nv_bfloat16 *relh = symaddrb(g_relh), *rell = symaddrb(g_rell);
    __nv_bfloat16 *qh = symaddrb(g_qh), *ql = symaddrb(g_ql);
    __nv_bfloat16 *valh = symaddrb(g_valh), *vall = symaddrb(g_vall);
    __nv_bfloat16 *atth = symaddrb(g_atth), *attl = symaddrb(g_attl);
    __nv_bfloat16 *Wh = symaddrb(g_Wh), *Wl = symaddrb(g_Wl);

    const int* nomask = (const int*)0;
    const float* nobias = (const float*)0;

    cudaFuncSetAttribute(k_logits_wmma, cudaFuncAttributeMaxDynamicSharedMemorySize, 2 * LSTG);

    // elementwise prep
    k_concat<<<(BB * KVL * DDim + 255) / 256, 256>>>(inputs, state);
    k_relT<<<(DDim * 512 + 255) / 256, 256>>>(rW);
    k_vrel<<<(HH * DDim * 32 + 255) / 256, 256>>>(vv, rW);
    k_qtrig<<<(TT * DDim + 255) / 256, 256>>>();
    k_ktrig<<<(KVL * DDim + 255) / 256, 256>>>();
    k_split<<<(BB * TT * DDim + 255) / 256, 256>>>(inputs, inh, inl, BB * TT * DDim);
    k_splitw<<<(4 * 262144 + 255) / 256, 256>>>(qW, kW, vW, oW);

    // query = inputs @ qW (rowmask)   M=1024 N=512 K=512
    gemmw<<<dim3(8, 8, 1), 256>>>(inh, inl, qWh, qWl, pQuery,
        512, 512, 512, 512, 0, 0, 0, 0, 0, 0, 1, mask, nobias, 0, 0);
    // key / value = concat @ W        M=2048 N=512 K=512
    gemmw<<<dim3(8, 16, 1), 256>>>(conh, conl, kWh, kWl, symaddr(g_key),
        512, 512, 512, 512, 0, 0, 0, 0, 0, 0, 1, nomask, nobias, 0, 0);
    gemmw<<<dim3(8, 16, 1), 256>>>(conh, conl, vWh, vWl, pValue,
        512, 512, 512, 512, 0, 0, 0, 0, 0, 0, 1, nomask, nobias, 0, 0);

    k_split<<<(BB * TT * 512 + 255) / 256, 256>>>(pQuery, qh, ql, BB * TT * 512);
    k_split<<<(BB * KVL * 512 + 255) / 256, 256>>>(pValue, valh, vall, BB * KVL * 512);

    // qv per-head: M=1024 N=512 K=64, + vrel bias
    gemmw<<<dim3(8, 8, HH), 256>>>(qh, ql, relh, rell, pQv,
        512, 512, 4096, 64,
        0, 64, 0, (long)UU * DDim, 0, 512, HH, nomask, pVrel, 512, 0);

    k_ubias<<<(BB * HH * KVL + 255) / 256, 256>>>(uW);
    k_bkey<<<(16 * KVL * UU + 255) / 256, 256>>>();
    k_acat_c<<<(16 * TT * UU + 255) / 256, 256>>>();
    k_acat_p<<<(16 * TT * DDim + 255) / 256, 256>>>();

    // logits on tensor cores (pipelined)
    k_logits_wmma<<<dim3(KVL / 128, TT / 128, 16), 256, 2 * LSTG>>>(mask, smask);

    k_softmax<<<BB * HH * TT, 256>>>();

    // attended = weights @ value   per (b,h): M=512 N=64 K=1024, causal K-truncation
    gemmw<<<dim3(1, 4, 16), 256>>>(Wh, Wl, valh, vall, pAtt,
        KVL, 512, 512, KVL,
        (long)HH * TT * KVL, (long)TT * KVL,
        (long)KVL * 512, 64,
        (long)TT * 512, 64, HH, nomask, nobias, 0, 1);

    k_split<<<(BB * TT * 512 + 255) / 256, 256>>>(pAtt, atth, attl, BB * TT * 512);

    // out = attended @ output_W    M=1024 N=512 K=512
    gemmw<<<dim3(8, 8, 1), 256>>>(atth, attl, oWh, oWl, out,
        512, 512, 512, 512, 0, 0, 0, 0, 0, 0, 1, nomask, nobias, 0, 0);
}

// round 11
// speedup vs baseline: 1.6070x; 1.1620x over previous
#include <cuda_runtime.h>
#include <cuda_bf16.h>
#include <mma.h>
#include <math.h>

using namespace nvcuda;

#define BB 2
#define TT 512
#define MMs 512
#define DDim 512
#define HH 8
#define UU 64
#define KVL 1024
#define LARGE_BIAS 10000.0f

// ---------------- scratch ----------------
__device__ __align__(128) float g_query[BB * TT * 512];
__device__ __align__(128) float g_keyval[BB * KVL * 1024];     // cols 0-511 key, 512-1023 value
__device__ __align__(128) float g_vrel[HH * DDim];
__device__ __align__(128) float g_qv[BB * TT * HH * DDim];
__device__ __align__(128) float g_ubias[BB * HH * KVL];
__device__ __align__(128) float g_logits[16 * TT * KVL];
__device__ __align__(128) float g_att[BB * TT * 512];
__device__ __align__(128) float2 g_qtrig[TT * DDim];
// bf16 hi/lo pools
__device__ __align__(128) __nv_bfloat16 g_inh[BB * TT * DDim], g_inl[BB * TT * DDim];
__device__ __align__(128) __nv_bfloat16 g_conh[BB * KVL * DDim], g_conl[BB * KVL * DDim];
__device__ __align__(128) __nv_bfloat16 g_qWh[512 * 512], g_qWl[512 * 512];
__device__ __align__(128) __nv_bfloat16 g_kvWh[512 * 1024], g_kvWl[512 * 1024];
__device__ __align__(128) __nv_bfloat16 g_oWh[512 * 512], g_oWl[512 * 512];
__device__ __align__(128) __nv_bfloat16 g_relh[512 * 512], g_rell[512 * 512];
__device__ __align__(128) __nv_bfloat16 g_qh[BB * TT * 512], g_ql[BB * TT * 512];
__device__ __align__(128) __nv_bfloat16 g_valh[BB * KVL * 512], g_vall[BB * KVL * 512];
__device__ __align__(128) __nv_bfloat16 g_atth[BB * TT * 512], g_attl[BB * TT * 512];
__device__ __align__(128) __nv_bfloat16 g_Wh[16 * TT * KVL], g_Wl[16 * TT * KVL];
__device__ __align__(128) __nv_bfloat16 g_Ktrig_h[KVL * 1024], g_Ktrig_l[KVL * 1024];
__device__ __align__(128) __nv_bfloat16 g_Bkey_h[16 * KVL * UU], g_Bkey_l[16 * KVL * UU];
__device__ __align__(128) __nv_bfloat16 g_Acat_h[16 * TT * 1088], g_Acat_l[16 * TT * 1088];

__device__ __forceinline__ void bsplit(float x, __nv_bfloat16& h, __nv_bfloat16& l) {
    h = __float2bfloat16(x);
    l = __float2bfloat16(x - __bfloat162float(h));
}
__device__ __forceinline__ void cpa16(void* sdst, const void* gsrc) {
    unsigned s = (unsigned)__cvta_generic_to_shared(sdst);
    asm volatile("cp.async.cg.shared.global [%0], [%1], 16;" :: "r"(s), "l"(gsrc));
}
#define CP_COMMIT() asm volatile("cp.async.commit_group;" ::: "memory")
#define CP_WAIT1()  asm volatile("cp.async.wait_group 1;" ::: "memory")
#define CP_WAIT0()  asm volatile("cp.async.wait_group 0;" ::: "memory")
__device__ __forceinline__ float ex2f(float x) {
    float r;
    asm("ex2.approx.ftz.f32 %0, %1;" : "=f"(r) : "f"(x));
    return r;
}

// ---------------- prep1: all input-only elementwise work, one launch ----------------
// segments (blocks of 256): concat 4096 | relT 1024 | vrel 512 | qtrig 1024 | ktrig 2048
//                           | split-in 2048 | split qW 1024 | split kvW 2048 | split oW 1024
//                           => total 14848 blocks
__global__ void __launch_bounds__(256) k_prep1(
    const float* __restrict__ in, const float* __restrict__ st,
    const float* __restrict__ rW, const float* __restrict__ vv,
    const float* __restrict__ qW, const float* __restrict__ kW,
    const float* __restrict__ vW, const float* __restrict__ oW)
{
    int blk = blockIdx.x;
    int tid = threadIdx.x;
    if (blk < 4096) {                                   // concat -> conh/conl
        int i = blk * 256 + tid;
        int d = i & 511, j = (i >> 9) & 1023, b = i >> 19;
        float v = (j < MMs) ? st[((size_t)(b * MMs + j)) * 512 + d]
                            : in[((size_t)(b * TT + (j - MMs))) * 512 + d];
        __nv_bfloat16 hi, lo; bsplit(v, hi, lo);
        g_conh[i] = hi; g_conl[i] = lo;
        return;
    }
    blk -= 4096;
    if (blk < 1024) {                                   // relT transpose+split
        int i = blk * 256 + tid;
        __nv_bfloat16 hi, lo; bsplit(rW[i], hi, lo);
        size_t o = (size_t)(i & 511) * 512 + (i >> 9);
        g_relh[o] = hi; g_rell[o] = lo;
        return;
    }
    blk -= 1024;
    if (blk < 512) {                                    // vrel (warp per output)
        int g = (blk * 256 + tid) >> 5, lane = tid & 31;
        int h = g >> 9, d = g & 511;
        const float* rp = rW + (size_t)d * 512 + h * 64;
        const float* vp = vv + h * 64;
        float s = rp[lane] * vp[lane] + rp[lane + 32] * vp[lane + 32];
#pragma unroll
        for (int o = 16; o > 0; o >>= 1) s += __shfl_xor_sync(~0u, s, o);
        if (!lane) g_vrel[h * 512 + d] = s;
        return;
    }
    blk -= 512;
    if (blk < 1024) {                                   // qtrig
        int i = blk * 256 + tid;
        int d = i & 511, qt = i >> 9;
        float invw = powf(10000.0f, -2.0f * (float)d / 512.0f);
        float off = (d & 1) ? 1.57079632679489662f : 0.0f;
        float s, c;
        sincosf((float)(qt + 512) * invw + off, &s, &c);
        g_qtrig[i] = make_float2(s, c);
        return;
    }
    blk -= 1024;
    if (blk < 2048) {                                   // ktrig
        int i = blk * 256 + tid;
        int d = i & 511, kv = i >> 9;
        float invw = powf(10000.0f, -2.0f * (float)d / 512.0f);
        float s, c;
        sincosf((float)kv * invw, &s, &c);
        __nv_bfloat16 ch, cl, sh, sl;
        bsplit(c, ch, cl); bsplit(s, sh, sl);
        __nv_bfloat162 vh, vl;
        vh.x = ch; vh.y = sh; vl.x = cl; vl.y = sl;
        *(__nv_bfloat162*)&g_Ktrig_h[(size_t)kv * 1024 + 2 * d] = vh;
        *(__nv_bfloat162*)&g_Ktrig_l[(size_t)kv * 1024 + 2 * d] = vl;
        return;
    }
    blk -= 2048;
    if (blk < 2048) {                                   // split inputs
        int i = blk * 256 + tid;
        __nv_bfloat16 hi, lo; bsplit(in[i], hi, lo);
        g_inh[i] = hi; g_inl[i] = lo;
        return;
    }
    blk -= 2048;
    if (blk < 1024) {                                   // split qW
        int i = blk * 256 + tid;
        __nv_bfloat16 hi, lo; bsplit(qW[i], hi, lo);
        g_qWh[i] = hi; g_qWl[i] = lo;
        return;
    }
    blk -= 1024;
    if (blk < 2048) {                                   // split kvW combined [512][1024]
        int i = blk * 256 + tid;
        int d = i >> 10, c = i & 1023;
        float x = (c < 512) ? kW[d * 512 + c] : vW[d * 512 + (c - 512)];
        __nv_bfloat16 hi, lo; bsplit(x, hi, lo);
        g_kvWh[i] = hi; g_kvWl[i] = lo;
        return;
    }
    blk -= 2048;
    {                                                   // split oW (1024 blocks)
        int i = blk * 256 + tid;
        __nv_bfloat16 hi, lo; bsplit(oW[i], hi, lo);
        g_oWh[i] = hi; g_oWl[i] = lo;
    }
}

// ---------------- prep2: after Q & KV gemms ----------------
// segments: split-q 2048 | split-val 4096 | ubias 64 | bkey 4096 | acat_c 2048 => 12352
__global__ void __launch_bounds__(256) k_prep2(const float* __restrict__ uW) {
    int blk = blockIdx.x;
    int tid = threadIdx.x;
    if (blk < 2048) {                                   // split query (524288 elems)
        int i = blk * 256 + tid;
        __nv_bfloat16 hi, lo; bsplit(g_query[i], hi, lo);
        g_qh[i] = hi; g_ql[i] = lo;
        return;
    }
    blk -= 2048;
    if (blk < 4096) {                                   // split value (1048576 elems: 2048 rows x 512)
        int i = blk * 256 + tid;
        int c = i & 511, row = i >> 9;
        __nv_bfloat16 hi, lo;
        bsplit(g_keyval[(size_t)row * 1024 + 512 + c], hi, lo);
        g_valh[i] = hi; g_vall[i] = lo;
        return;
    }
    blk -= 4096;
    if (blk < 64) {                                     // ubias
        int i = blk * 256 + tid;
        int kv = i & 1023, h = (i >> 10) & 7, b = i >> 13;
        const float* kp = g_keyval + ((size_t)(b * KVL + kv)) * 1024 + h * 64;
        const float* up = uW + h * 64;
        float s = 0.f;
#pragma unroll
        for (int u = 0; u < 64; u++) s = fmaf(kp[u], up[u], s);
        g_ubias[i] = s;
        return;
    }
    blk -= 64;
    if (blk < 4096) {                                   // bkey
        int i = blk * 256 + tid;
        int u = i & 63, kv = (i >> 6) & 1023, bh = i >> 16;
        int b = bh >> 3, h = bh & 7;
        __nv_bfloat16 hi, lo;
        bsplit(g_keyval[(size_t)(b * KVL + kv) * 1024 + h * 64 + u], hi, lo);
        g_Bkey_h[i] = hi; g_Bkey_l[i] = lo;
        return;
    }
    blk -= 4096;
    {                                                   // acat_c (2048 blocks)
        int i = blk * 256 + tid;
        int u = i & 63, qt = (i >> 6) & 511, bh = i >> 15;
        int b = bh >> 3, h = bh & 7;
        __nv_bfloat16 hi, lo;
        bsplit(g_query[(size_t)(b * TT + qt) * 512 + h * 64 + u], hi, lo);
        size_t o = ((size_t)bh * TT + qt) * 1088 + u;
        g_Acat_h[o] = hi; g_Acat_l[o] = lo;
    }
}

__global__ void k_acat_p() {
    int i = blockIdx.x * blockDim.x + threadIdx.x;
    if (i >= 16 * TT * DDim) return;
    int d = i & 511, qt = (i >> 9) & 511, bh = i >> 18;
    int b = bh >> 3, h = bh & 7;
    float q = g_qv[(size_t)(b * TT + qt) * 4096 + h * 512 + d];
    float2 tr = g_qtrig[qt * 512 + d];
    __nv_bfloat16 sh, sl, ch, cl;
    bsplit(q * tr.x, sh, sl);
    bsplit(-q * tr.y, ch, cl);
    size_t o = ((size_t)bh * TT + qt) * 1088 + 64 + 2 * d;
    __nv_bfloat162 vh, vl;
    vh.x = sh; vh.y = ch; vl.x = sl; vl.y = cl;
    *(__nv_bfloat162*)&g_Acat_h[o] = vh;
    *(__nv_bfloat162*)&g_Acat_l[o] = vl;
}
__global__ void k_split(const float* __restrict__ s, __nv_bfloat16* __restrict__ h,
                        __nv_bfloat16* __restrict__ l, int n) {
    int i = blockIdx.x * blockDim.x + threadIdx.x;
    if (i >= n) return;
    __nv_bfloat16 hi, lo; bsplit(s[i], hi, lo);
    h[i] = hi; l[i] = lo;
}

// ---------------- WMMA hi/lo GEMM, cp.async 2-stage pipelined ----------------
#define PADA 40
#define PADB 72
#define OUTLD 20
#define GA 10240                 // 128*PADA*2 bytes
#define GB 4608                  // 32*PADB*2 bytes
#define GSTG (2 * GA + 2 * GB)   // 29696 per stage

__global__ void __launch_bounds__(256) gemmw(
    const __nv_bfloat16* __restrict__ Ah, const __nv_bfloat16* __restrict__ Al,
    const __nv_bfloat16* __restrict__ Bh, const __nv_bfloat16* __restrict__ Bl,
    float* __restrict__ C,
    int lda, int ldb, int ldc, int Kdim,
    long az1, long az2, long bz1, long bz2, long cz1, long cz2, int Z2,
    const int* __restrict__ rowmask, const float* __restrict__ bias, long biasz2,
    int causal)
{
    extern __shared__ char dsm[];
    int z = blockIdx.z, z1 = z / Z2, z2 = z - z1 * Z2;
    const __nv_bfloat16* Ahp = Ah + (size_t)z1 * az1 + (size_t)z2 * az2;
    const __nv_bfloat16* Alp = Al + (size_t)z1 * az1 + (size_t)z2 * az2;
    const __nv_bfloat16* Bhp = Bh + (size_t)z1 * bz1 + (size_t)z2 * bz2;
    const __nv_bfloat16* Blp = Bl + (size_t)z1 * bz1 + (size_t)z2 * bz2;
    float* Cp = C + (size_t)z1 * cz1 + (size_t)z2 * cz2;
    const float* biasp = bias ? (bias + (size_t)z2 * biasz2) : (const float*)0;

    int m0 = blockIdx.y * 128, n0 = blockIdx.x * 64;
    int tid = threadIdx.x, wid = tid >> 5, lane = tid & 31;
    int wy = wid >> 1, wx = wid & 1;

    wmma::fragment<wmma::accumulator, 16, 16, 16, float> acc[2][2];
#pragma unroll
    for (int mi = 0; mi < 2; mi++)
#pragma unroll
        for (int ni = 0; ni < 2; ni++) wmma::fill_fragment(acc[mi][ni], 0.f);

    int Klim = Kdim;
    if (causal) {
        int km = m0 + 640;
        Klim = (km < Kdim) ? ((km + 31) & ~31) : Kdim;
    }
    int nCh = Klim >> 5;

    auto issue = [&](int c, int s) {
        int kc = c * 32;
        char* base = dsm + s * GSTG;
#pragma unroll
        for (int t = tid; t < 512; t += 256) {
            int row = t >> 2, seg = (t & 3) * 8;
            size_t go = (size_t)(m0 + row) * lda + kc + seg;
            size_t so = ((size_t)row * PADA + seg) * 2;
            cpa16(base + so, Ahp + go);
            cpa16(base + GA + so, Alp + go);
        }
        {
            int row = tid >> 3, seg = (tid & 7) * 8;
            size_t go = (size_t)(kc + row) * ldb + n0 + seg;
            size_t so = ((size_t)row * PADB + seg) * 2;
            cpa16(base + 2 * GA + so, Bhp + go);
            cpa16(base + 2 * GA + GB + so, Blp + go);
        }
        CP_COMMIT();
    };

    issue(0, 0);
    for (int c = 0; c < nCh; c++) {
        if (c + 1 < nCh) { issue(c + 1, (c + 1) & 1); CP_WAIT1(); }
        else             { CP_WAIT0(); }
        __syncthreads();
        char* base = dsm + (c & 1) * GSTG;
        __nv_bfloat16* sAh = (__nv_bfloat16*)base;
        __nv_bfloat16* sAl = (__nv_bfloat16*)(base + GA);
        __nv_bfloat16* sBh = (__nv_bfloat16*)(base + 2 * GA);
        __nv_bfloat16* sBl = (__nv_bfloat16*)(base + 2 * GA + GB);
#pragma unroll
        for (int ks = 0; ks < 2; ks++) {
            wmma::fragment<wmma::matrix_a, 16, 16, 16, __nv_bfloat16, wmma::row_major> fah[2], fal[2];
            wmma::fragment<wmma::matrix_b, 16, 16, 16, __nv_bfloat16, wmma::row_major> fbh[2], fbl[2];
#pragma unroll
            for (int mi = 0; mi < 2; mi++) {
                wmma::load_matrix_sync(fah[mi], &sAh[(wy * 32 + mi * 16) * PADA + ks * 16], PADA);
                wmma::load_matrix_sync(fal[mi], &sAl[(wy * 32 + mi * 16) * PADA + ks * 16], PADA);
            }
#pragma unroll
            for (int ni = 0; ni < 2; ni++) {
                wmma::load_matrix_sync(fbh[ni], &sBh[ks * 16 * PADB + wx * 32 + ni * 16], PADB);
                wmma::load_matrix_sync(fbl[ni], &sBl[ks * 16 * PADB + wx * 32 + ni * 16], PADB);
            }
#pragma unroll
            for (int mi = 0; mi < 2; mi++)
#pragma unroll
                for (int ni = 0; ni < 2; ni++) {
                    wmma::mma_sync(acc[mi][ni], fah[mi], fbh[ni], acc[mi][ni]);
                    wmma::mma_sync(acc[mi][ni], fah[mi], fbl[ni], acc[mi][ni]);
                    wmma::mma_sync(acc[mi][ni], fal[mi], fbh[ni], acc[mi][ni]);
                }
        }
        __syncthreads();
    }

    float* sOut = (float*)dsm + wid * 16 * OUTLD;
#pragma unroll
    for (int mi = 0; mi < 2; mi++)
#pragma unroll
        for (int ni = 0; ni < 2; ni++) {
            wmma::store_matrix_sync(sOut, acc[mi][ni], OUTLD, wmma::mem_row_major);
            __syncwarp();
#pragma unroll
            for (int e = 0; e < 8; e++) {
                int idx = lane * 8 + e;
                int r = idx >> 4, cc = idx & 15;
                int mg = m0 + wy * 32 + mi * 16 + r;
                int ng = n0 + wx * 32 + ni * 16 + cc;
                float x = sOut[r * OUTLD + cc];
                if (biasp) x += biasp[ng];
                if (rowmask) x *= rowmask[mg] ? 1.f : 0.f;
                Cp[(size_t)mg * ldc + ng] = x;
            }
            __syncwarp();
        }
}

// ---------------- WMMA logits (proven 2-stage pipelined version) ----------------
#define LTILE 10240
#define LSTG  (4 * LTILE)

__global__ void __launch_bounds__(256, 1) k_logits_wmma(
    const int* __restrict__ qmask, const int* __restrict__ smask)
{
    extern __shared__ char dsm[];
    int tid = threadIdx.x, wid = tid >> 5, lane = tid & 31;
    int kv0 = blockIdx.x * 128, qt0 = blockIdx.y * 128, bh = blockIdx.z;
    int b = bh >> 3;

    if (kv0 >= qt0 + 640) {
        float4 neg = make_float4(-LARGE_BIAS, -LARGE_BIAS, -LARGE_BIAS, -LARGE_BIAS);
        for (int t = tid; t < 128 * 32; t += 256) {
            int r = t >> 5, c = (t & 31) * 4;
            *(float4*)&g_logits[((size_t)bh * TT + qt0 + r) * KVL + kv0 + c] = neg;
        }
        return;
    }

    int wy = wid >> 2, wx = wid & 3;
    wmma::fragment<wmma::accumulator, 16, 16, 16, float> acc[4][2];
#pragma unroll
    for (int mi = 0; mi < 4; mi++)
#pragma unroll
        for (int ni = 0; ni < 2; ni++) wmma::fill_fragment(acc[mi][ni], 0.f);

    const __nv_bfloat16* Ah = g_Acat_h + ((size_t)bh * TT + qt0) * 1088;
    const __nv_bfloat16* Al = g_Acat_l + ((size_t)bh * TT + qt0) * 1088;
    const __nv_bfloat16* BKh = g_Bkey_h + (size_t)bh * KVL * 64;
    const __nv_bfloat16* BKl = g_Bkey_l + (size_t)bh * KVL * 64;

    auto issue = [&](int kc, int s) {
        const __nv_bfloat16 *Bhp, *Blp;
        size_t bld;
        int bcol;
        if (kc < 2) { Bhp = BKh; Blp = BKl; bld = 64; bcol = kc * 32; }
        else        { Bhp = g_Ktrig_h; Blp = g_Ktrig_l; bld = 1024; bcol = (kc - 2) * 32; }
        char* base = dsm + s * LSTG;
#pragma unroll
        for (int t = tid; t < 512; t += 256) {
            int row = t >> 2, seg = (t & 3) * 8;
            size_t so = ((size_t)row * PADA + seg) * 2;
            cpa16(base + so,             Ah + (size_t)row * 1088 + kc * 32 + seg);
            cpa16(base + LTILE + so,     Al + (size_t)row * 1088 + kc * 32 + seg);
            cpa16(base + 2 * LTILE + so, Bhp + (size_t)(kv0 + row) * bld + bcol + seg);
            cpa16(base + 3 * LTILE + so, Blp + (size_t)(kv0 + row) * bld + bcol + seg);
        }
        CP_COMMIT();
    };

    issue(0, 0);
    for (int kc = 0; kc < 34; kc++) {
        if (kc + 1 < 34) { issue(kc + 1, (kc + 1) & 1); CP_WAIT1(); }
        else             { CP_WAIT0(); }
        __syncthreads();
        char* base = dsm + (kc & 1) * LSTG;
        __nv_bfloat16* sAh = (__nv_bfloat16*)base;
        __nv_bfloat16* sAl = (__nv_bfloat16*)(base + LTILE);
        __nv_bfloat16* sBh = (__nv_bfloat16*)(base + 2 * LTILE);
        __nv_bfloat16* sBl = (__nv_bfloat16*)(base + 3 * LTILE);
#pragma unroll
        for (int ks = 0; ks < 2; ks++) {
            wmma::fragment<wmma::matrix_b, 16, 16, 16, __nv_bfloat16, wmma::col_major> fbh[2], fbl[2];
#pragma unroll
            for (int ni = 0; ni < 2; ni++) {
                wmma::load_matrix_sync(fbh[ni], &sBh[(wx * 32 + ni * 16) * PADA + ks * 16], PADA);
                wmma::load_matrix_sync(fbl[ni], &sBl[(wx * 32 + ni * 16) * PADA + ks * 16], PADA);
            }
#pragma unroll
            for (int mi = 0; mi < 4; mi++) {
                wmma::fragment<wmma::matrix_a, 16, 16, 16, __nv_bfloat16, wmma::row_major> fah, fal;
                wmma::load_matrix_sync(fah, &sAh[(wy * 64 + mi * 16) * PADA + ks * 16], PADA);
                wmma::load_matrix_sync(fal, &sAl[(wy * 64 + mi * 16) * PADA + ks * 16], PADA);
#pragma unroll
                for (int ni = 0; ni < 2; ni++) {
                    wmma::mma_sync(acc[mi][ni], fah, fbh[ni], acc[mi][ni]);
                    wmma::mma_sync(acc[mi][ni], fah, fbl[ni], acc[mi][ni]);
                    wmma::mma_sync(acc[mi][ni], fal, fbh[ni], acc[mi][ni]);
                }
            }
        }
        __syncthreads();
    }

    float* sOut = (float*)dsm + wid * 16 * OUTLD;
    const float* ub = g_ubias + (size_t)bh * KVL;
#pragma unroll
    for (int mi = 0; mi < 4; mi++)
#pragma unroll
        for (int ni = 0; ni < 2; ni++) {
            wmma::store_matrix_sync(sOut, acc[mi][ni], OUTLD, wmma::mem_row_major);
            __syncwarp();
#pragma unroll
            for (int e = 0; e < 8; e++) {
                int idx = lane * 8 + e;
                int r = idx >> 4, c = idx & 15;
                int qt = qt0 + wy * 64 + mi * 16 + r;
                int kv = kv0 + wx * 32 + ni * 16 + c;
                float x = (sOut[r * OUTLD + c] + ub[kv]) * 0.125f;
                if (kv - qt >= 513) x -= LARGE_BIAS;
                int cm = (kv < MMs) ? smask[b * MMs + kv] : qmask[b * TT + (kv - MMs)];
                if (!cm) x -= LARGE_BIAS;
                g_logits[((size_t)bh * TT + qt) * KVL + kv] = x;
            }
            __syncwarp();
        }
}

// ---------------- softmax -> bf16 hi/lo weights (ex2 + warp-skip) ----------------
__global__ void __launch_bounds__(256) k_softmax() {
    size_t ro = (size_t)blockIdx.x * KVL;
    float* row = g_logits + ro;
    int tid = threadIdx.x, lane = tid & 31, wid = tid >> 5;
    __shared__ float red[8];
    __shared__ float bc;
    float v[4], mx = -1e30f;
#pragma unroll
    for (int i = 0; i < 4; i++) { v[i] = row[tid + i * 256]; mx = fmaxf(mx, v[i]); }
#pragma unroll
    for (int o = 16; o > 0; o >>= 1) mx = fmaxf(mx, __shfl_xor_sync(~0u, mx, o));
    if (!lane) red[wid] = mx;
    __syncthreads();
    if (!wid) {
        float m2 = (lane < 8) ? red[lane] : -1e30f;
#pragma unroll
        for (int o = 16; o > 0; o >>= 1) m2 = fmaxf(m2, __shfl_xor_sync(~0u, m2, o));
        if (!lane) bc = m2;
    }
    __syncthreads();
    mx = bc;
    float s = 0.f;
#pragma unroll
    for (int i = 0; i < 4; i++) {
        float t = v[i] - mx;
        if (__all_sync(~0u, t < -30.f)) v[i] = 0.f;
        else v[i] = ex2f(t * 1.44269504f);
        s += v[i];
    }
#pragma unroll
    for (int o = 16; o > 0; o >>= 1) s += __shfl_xor_sync(~0u, s, o);
    __syncthreads();
    if (!lane) red[wid] = s;
    __syncthreads();
    if (!wid) {
        float s2 = (lane < 8) ? red[lane] : 0.f;
#pragma unroll
        for (int o = 16; o > 0; o >>= 1) s2 += __shfl_xor_sync(~0u, s2, o);
        if (!lane) bc = s2;
    }
    __syncthreads();
    float inv = 1.f / bc;
#pragma unroll
    for (int i = 0; i < 4; i++) {
        float w = v[i] * inv;
        __nv_bfloat16 hi, lo;
        bsplit(w, hi, lo);
        g_Wh[ro + tid + i * 256] = hi;
        g_Wl[ro + tid + i * 256] = lo;
    }
}

// ---------------- host ----------------
static float* symaddr(const void* s) { void* p = 0; cudaGetSymbolAddress(&p, s); return (float*)p; }
static __nv_bfloat16* symaddrb(const void* s) { void* p = 0; cudaGetSymbolAddress(&p, s); return (__nv_bfloat16*)p; }

extern "C" void kernel_launch(void* const* d_in, const int* in_sizes, int n_in,
                              void* d_out, int out_size) {
    (void)in_sizes; (void)n_in; (void)out_size;
    const float* inputs = (const float*)d_in[0];
    const float* state  = (const float*)d_in[1];
    const int* mask     = (const int*)d_in[2];
    const int* smask    = (const int*)d_in[3];
    const float* qW = (const float*)d_in[4];
    const float* kW = (const float*)d_in[5];
    const float* rW = (const float*)d_in[6];
    const float* vW = (const float*)d_in[7];
    const float* uW = (const float*)d_in[8];
    const float* vv = (const float*)d_in[9];
    const float* oW = (const float*)d_in[10];
    float* out = (float*)d_out;

    float* pQuery  = symaddr(g_query);
    float* pKeyVal = symaddr(g_keyval);
    float* pVrel   = symaddr(g_vrel);
    float* pQv     = symaddr(g_qv);
    float* pAtt    = symaddr(g_att);

    __nv_bfloat16 *inh = symaddrb(g_inh), *inl = symaddrb(g_inl);
    __nv_bfloat16 *conh = symaddrb(g_conh), *conl = symaddrb(g_conl);
    __nv_bfloat16 *qWh = symaddrb(g_qWh), *qWl = symaddrb(g_qWl);
    __nv_bfloat16 *kvWh = symaddrb(g_kvWh), *kvWl = symaddrb(g_kvWl);
    __nv_bfloat16 *oWh = symaddrb(g_oWh), *oWl = symaddrb(g_oWl);
    __nv_bfloat16 *relh = symaddrb(g_relh), *rell = symaddrb(g_rell);
    __nv_bfloat16 *qh = symaddrb(g_qh), *ql = symaddrb(g_ql);
    __nv_bfloat16 *valh = symaddrb(g_valh), *vall = symaddrb(g_vall);
    __nv_bfloat16 *atth = symaddrb(g_atth), *attl = symaddrb(g_attl);
    __nv_bfloat16 *Wh = symaddrb(g_Wh), *Wl = symaddrb(g_Wl);

    const int* nomask = (const int*)0;
    const float* nobias = (const float*)0;

    cudaFuncSetAttribute(k_logits_wmma, cudaFuncAttributeMaxDynamicSharedMemorySize, 2 * LSTG);
    cudaFuncSetAttribute(gemmw, cudaFuncAttributeMaxDynamicSharedMemorySize, 2 * GSTG);

    // prep1: all input-only elementwise work  (14848 blocks)
    k_prep1<<<14848, 256>>>(inputs, state, rW, vv, qW, kW, vW, oW);

    // query = inputs @ qW (rowmask)   M=1024 N=512 K=512
    gemmw<<<dim3(8, 8, 1), 256, 2 * GSTG>>>(inh, inl, qWh, qWl, pQuery,
        512, 512, 512, 512, 0, 0, 0, 0, 0, 0, 1, mask, nobias, 0, 0);
    // keyval = concat @ [kW|vW]       M=2048 N=1024 K=512
    gemmw<<<dim3(16, 16, 1), 256, 2 * GSTG>>>(conh, conl, kvWh, kvWl, pKeyVal,
        512, 1024, 1024, 512, 0, 0, 0, 0, 0, 0, 1, nomask, nobias, 0, 0);

    // prep2: split q, split value, ubias, bkey, acat_c  (12352 blocks)
    k_prep2<<<12352, 256>>>(uW);

    // qv per-head: M=1024 N=512 K=64, + vrel bias
    gemmw<<<dim3(8, 8, HH), 256, 2 * GSTG>>>(qh, ql, relh, rell, pQv,
        512, 512, 4096, 64,
        0, 64, 0, (long)UU * DDim, 0, 512, HH, nomask, pVrel, 512, 0);

    k_acat_p<<<(16 * TT * DDim + 255) / 256, 256>>>();

    // logits on tensor cores (pipelined)
    k_logits_wmma<<<dim3(KVL / 128, TT / 128, 16), 256, 2 * LSTG>>>(mask, smask);

    k_softmax<<<16 * TT, 256>>>();

    // attended = weights @ value   per (b,h): M=512 N=64 K=1024, causal K-truncation
    gemmw<<<dim3(1, 4, 16), 256, 2 * GSTG>>>(Wh, Wl, valh, vall, pAtt,
        KVL, 512, 512, KVL,
        (long)HH * TT * KVL, (long)TT * KVL,
        (long)KVL * 512, 64,
        (long)TT * 512, 64, HH, nomask, nobias, 0, 1);

    k_split<<<(BB * TT * 512 + 255) / 256, 256>>>(pAtt, atth, attl, BB * TT * 512);

    // out = attended @ output_W    M=1024 N=512 K=512
    gemmw<<<dim3(8, 8, 1), 256, 2 * GSTG>>>(atth, attl, oWh, oWl, out,
        512, 512, 512, 512, 0, 0, 0, 0, 0, 0, 1, nomask, nobias, 0, 0);
}